// round 1
// baseline (speedup 1.0000x reference)
#include <cuda_runtime.h>
#include <math.h>

#define N_PTS 100000
#define KNB   16
#define CIN   128
#define COUT  256
#define NKP   15
#define CXJ   131            // CIN + 3
#define KTOT  1965           // NKP * CXJ
#define KPAD  1968           // padded to multiple of 16

#define BM 128
#define BN 128
#define BK 16

// Scratch (allocation-free rule: __device__ globals)
__device__ float g_agg[(size_t)N_PTS * KPAD];   // [N][KPAD], pad zero-filled
__device__ float g_wt[(size_t)KPAD * COUT];     // [KPAD][COUT]

// SCALE = 0.3^2*2 + 1e-10 ; we multiply by 1/SCALE
__device__ __constant__ float d_dummy; // keep compiler happy if unused

// ---------------------------------------------------------------------------
// Weight transpose: g_wt[(m*131+c)*256 + o] = conv_w[o][c][m]; pad rows -> 0
// ---------------------------------------------------------------------------
__global__ void wt_transpose_kernel(const float* __restrict__ conv_w) {
    int e = blockIdx.x * blockDim.x + threadIdx.x;
    if (e >= KPAD * COUT) return;
    int kk = e / COUT;
    int o  = e - kk * COUT;
    float v = 0.0f;
    if (kk < KTOT) {
        int m = kk / CXJ;
        int c = kk - m * CXJ;
        v = conv_w[((size_t)o * CXJ + c) * NKP + m];
    }
    g_wt[e] = v;
}

// ---------------------------------------------------------------------------
// Preprocess: per point n, compute agg[m][c] = sum_k corr[m][k]*xj[k][c]
// ---------------------------------------------------------------------------
__global__ __launch_bounds__(256) void preprocess_kernel(
    const float* __restrict__ p,
    const float* __restrict__ x,
    const float* __restrict__ kp,
    const int*   __restrict__ idx)
{
    const int n   = blockIdx.x;
    const int tid = threadIdx.x;

    __shared__ float s_pj[KNB][3];
    __shared__ float s_l2[KNB];
    __shared__ float s_inv;
    __shared__ float s_corr[NKP][KNB];
    __shared__ float s_xj[KNB][CXJ + 1];
    __shared__ int   s_idx[KNB];

    if (tid < KNB) s_idx[tid] = idx[(size_t)n * KNB + tid];
    __syncthreads();

    const float px = p[3 * n + 0];
    const float py = p[3 * n + 1];
    const float pz = p[3 * n + 2];

    if (tid < KNB) {
        int j = s_idx[tid];
        float dx = p[3 * j + 0] - px;
        float dy = p[3 * j + 1] - py;
        float dz = p[3 * j + 2] - pz;
        s_pj[tid][0] = dx; s_pj[tid][1] = dy; s_pj[tid][2] = dz;
        s_l2[tid] = sqrtf(dx * dx + dy * dy + dz * dz);
    }
    __syncthreads();

    if (tid == 0) {
        float mx = s_l2[0];
        #pragma unroll
        for (int k = 1; k < KNB; k++) mx = fmaxf(mx, s_l2[k]);
        s_inv = 1.0f / (mx + 1e-10f);
    }
    __syncthreads();

    const float inv = s_inv;
    if (tid < KNB) {
        s_pj[tid][0] *= inv;
        s_pj[tid][1] *= inv;
        s_pj[tid][2] *= inv;
    }
    __syncthreads();

    // corr[m][k] = exp(-||kp[m]-pj[k]||^2 / SCALE)
    const float INV_SCALE = (float)(1.0 / (0.3 * 0.3 * 2.0 + 1e-10));
    if (tid < NKP * KNB) {
        int m = tid / KNB;
        int k = tid - m * KNB;
        float dx = kp[m * 3 + 0] - s_pj[k][0];
        float dy = kp[m * 3 + 1] - s_pj[k][1];
        float dz = kp[m * 3 + 2] - s_pj[k][2];
        s_corr[m][k] = expf(-(dx * dx + dy * dy + dz * dz) * INV_SCALE);
    }

    // xj[k][c] = (c<3 ? pj : x[j][c-3])
    for (int e = tid; e < KNB * CXJ; e += 256) {
        int k = e / CXJ;
        int c = e - k * CXJ;
        float v;
        if (c < 3) v = s_pj[k][c];
        else       v = x[(size_t)s_idx[k] * CIN + (c - 3)];
        s_xj[k][c] = v;
    }
    __syncthreads();

    // agg and write (pad region -> 0)
    float* dst = &g_agg[(size_t)n * KPAD];
    for (int o = tid; o < KPAD; o += 256) {
        float acc = 0.0f;
        if (o < KTOT) {
            int m = o / CXJ;
            int c = o - m * CXJ;
            #pragma unroll
            for (int k = 0; k < KNB; k++)
                acc = fmaf(s_corr[m][k], s_xj[k][c], acc);
        }
        dst[o] = acc;
    }
}

// ---------------------------------------------------------------------------
// GEMM: out[n][o] = relu( (sum_kk agg[n][kk]*wt[kk][o] + b[o] - mean)*s + beta )
// 128x128 tile, BK=16, 256 threads, 8x8 per-thread microtile
// ---------------------------------------------------------------------------
__global__ __launch_bounds__(256) void gemm_bn_relu_kernel(
    const float* __restrict__ conv_b,
    const float* __restrict__ bn_gamma,
    const float* __restrict__ bn_beta,
    const float* __restrict__ bn_mean,
    const float* __restrict__ bn_var,
    float* __restrict__ out)
{
    __shared__ float As[BK][BM + 4];   // transposed A tile, padded
    __shared__ float Bs[BK][BN];

    const int tid = threadIdx.x;
    const int m0  = blockIdx.x * BM;
    const int n0  = blockIdx.y * BN;
    const int tx  = tid & 15;          // 16 across N
    const int ty  = tid >> 4;          // 16 across M

    float acc[8][8];
    #pragma unroll
    for (int i = 0; i < 8; i++)
        #pragma unroll
        for (int j = 0; j < 8; j++) acc[i][j] = 0.0f;

    for (int k0 = 0; k0 < KPAD; k0 += BK) {
        // ---- load A tile (128 rows x 16 k), transpose into As[k][m] ----
        #pragma unroll
        for (int L = 0; L < 2; L++) {
            int v   = tid + L * 256;          // 0..511
            int row = v >> 2;                 // 0..127
            int kq  = (v & 3) * 4;            // 0,4,8,12
            float4 a = make_float4(0.f, 0.f, 0.f, 0.f);
            int gr = m0 + row;
            if (gr < N_PTS)
                a = *reinterpret_cast<const float4*>(
                        &g_agg[(size_t)gr * KPAD + k0 + kq]);
            As[kq + 0][row] = a.x;
            As[kq + 1][row] = a.y;
            As[kq + 2][row] = a.z;
            As[kq + 3][row] = a.w;
        }
        // ---- load B tile (16 k x 128 cols) ----
        #pragma unroll
        for (int L = 0; L < 2; L++) {
            int v  = tid + L * 256;           // 0..511
            int r  = v >> 5;                  // 0..15
            int cq = (v & 31) * 4;            // 0..124
            float4 b = *reinterpret_cast<const float4*>(
                           &g_wt[(size_t)(k0 + r) * COUT + n0 + cq]);
            *reinterpret_cast<float4*>(&Bs[r][cq]) = b;
        }
        __syncthreads();

        #pragma unroll
        for (int k = 0; k < BK; k++) {
            float a_frag[8], b_frag[8];
            *(float4*)&a_frag[0] = *(const float4*)&As[k][ty * 8];
            *(float4*)&a_frag[4] = *(const float4*)&As[k][ty * 8 + 4];
            *(float4*)&b_frag[0] = *(const float4*)&Bs[k][tx * 8];
            *(float4*)&b_frag[4] = *(const float4*)&Bs[k][tx * 8 + 4];
            #pragma unroll
            for (int i = 0; i < 8; i++)
                #pragma unroll
                for (int j = 0; j < 8; j++)
                    acc[i][j] = fmaf(a_frag[i], b_frag[j], acc[i][j]);
        }
        __syncthreads();
    }

    // ---- epilogue: bias + BN + ReLU ----
    float sc[8], bi[8];
    #pragma unroll
    for (int j = 0; j < 8; j++) {
        int col = n0 + tx * 8 + j;
        float s = bn_gamma[col] * rsqrtf(bn_var[col] + 1e-5f);
        sc[j] = s;
        bi[j] = (conv_b[col] - bn_mean[col]) * s + bn_beta[col];
    }
    #pragma unroll
    for (int i = 0; i < 8; i++) {
        int row = m0 + ty * 8 + i;
        if (row < N_PTS) {
            #pragma unroll
            for (int j = 0; j < 8; j++) {
                float yv = fmaf(acc[i][j], sc[j], bi[j]);
                out[(size_t)row * COUT + n0 + tx * 8 + j] = fmaxf(yv, 0.0f);
            }
        }
    }
}

// ---------------------------------------------------------------------------
extern "C" void kernel_launch(void* const* d_in, const int* in_sizes, int n_in,
                              void* d_out, int out_size) {
    const float* p     = (const float*)d_in[0];
    const float* x     = (const float*)d_in[1];
    const float* kp    = (const float*)d_in[2];
    const float* w     = (const float*)d_in[3];
    const float* b     = (const float*)d_in[4];
    const float* gamma = (const float*)d_in[5];
    const float* beta  = (const float*)d_in[6];
    const float* mean  = (const float*)d_in[7];
    const float* var   = (const float*)d_in[8];
    const int*   idx   = (const int*)d_in[9];
    float* out = (float*)d_out;

    wt_transpose_kernel<<<(KPAD * COUT + 255) / 256, 256>>>(w);
    preprocess_kernel<<<N_PTS, 256>>>(p, x, kp, idx);
    dim3 grid((N_PTS + BM - 1) / BM, COUT / BN);
    gemm_bn_relu_kernel<<<grid, 256>>>(b, gamma, beta, mean, var, out);
}

// round 3
// speedup vs baseline: 1.9473x; 1.9473x over previous
#include <cuda_runtime.h>
#include <cuda_bf16.h>
#include <cstdint>
#include <math.h>

#define N_PTS 100000
#define KNB   16
#define CIN   128
#define COUT  256
#define NKP   15
#define CXJ   131            // CIN + 3
#define KTOT  1965           // NKP * CXJ
#define KP2   1984           // padded: 31 * 64
#define NCHUNK 31            // K chunks of 64

// ---------------- scratch (allocation-free rule: __device__ globals) --------
__device__ __align__(128) __nv_bfloat16 g_agg_hi[(size_t)N_PTS * KP2];
__device__ __align__(128) __nv_bfloat16 g_agg_lo[(size_t)N_PTS * KP2];
__device__ __align__(128) __nv_bfloat16 g_wbt_hi[(size_t)KP2 * COUT];  // [k][n]
__device__ __align__(128) __nv_bfloat16 g_wbt_lo[(size_t)KP2 * COUT];  // [k][n]

// ---------------- PTX helpers (sm_103 base target only!) --------------------
__device__ __forceinline__ uint32_t smem_u32(const void* p) {
    uint32_t a;
    asm("{ .reg .u64 t; cvta.to.shared.u64 t, %1; cvt.u32.u64 %0, t; }"
        : "=r"(a) : "l"(p));
    return a;
}

__device__ __forceinline__ void cp_async16(uint32_t dst, const void* src,
                                           uint32_t srcsize) {
    asm volatile("cp.async.cg.shared.global [%0], [%1], 16, %2;"
                 :: "r"(dst), "l"(src), "r"(srcsize) : "memory");
}

__device__ __forceinline__ void cp_commit() {
    asm volatile("cp.async.commit_group;" ::: "memory");
}

template <int N>
__device__ __forceinline__ void cp_wait() {
    asm volatile("cp.async.wait_group %0;" :: "n"(N) : "memory");
}

__device__ __forceinline__ void ldsm_x4(uint32_t* r, uint32_t addr) {
    asm volatile("ldmatrix.sync.aligned.m8n8.x4.shared.b16 {%0,%1,%2,%3}, [%4];"
                 : "=r"(r[0]), "=r"(r[1]), "=r"(r[2]), "=r"(r[3]) : "r"(addr));
}

__device__ __forceinline__ void ldsm_x4_t(uint32_t* r, uint32_t addr) {
    asm volatile("ldmatrix.sync.aligned.m8n8.x4.trans.shared.b16 {%0,%1,%2,%3}, [%4];"
                 : "=r"(r[0]), "=r"(r[1]), "=r"(r[2]), "=r"(r[3]) : "r"(addr));
}

__device__ __forceinline__ void mma_bf16(float* c, const uint32_t* a,
                                         const uint32_t* b) {
    asm volatile(
        "mma.sync.aligned.m16n8k16.row.col.f32.bf16.bf16.f32 "
        "{%0,%1,%2,%3}, {%4,%5,%6,%7}, {%8,%9}, {%0,%1,%2,%3};"
        : "+f"(c[0]), "+f"(c[1]), "+f"(c[2]), "+f"(c[3])
        : "r"(a[0]), "r"(a[1]), "r"(a[2]), "r"(a[3]), "r"(b[0]), "r"(b[1]));
}

// ---------------------------------------------------------------------------
// Weight prep: g_wbt[k][n] = split_bf16(conv_w[n][k%131][k/131]); pad -> 0
// ---------------------------------------------------------------------------
__global__ void wt_split_kernel(const float* __restrict__ conv_w) {
    int e = blockIdx.x * blockDim.x + threadIdx.x;
    if (e >= KP2 * COUT) return;
    int k = e / COUT;
    int n = e - k * COUT;
    float v = 0.0f;
    if (k < KTOT) {
        int m = k / CXJ;
        int c = k - m * CXJ;
        v = conv_w[((size_t)n * CXJ + c) * NKP + m];
    }
    __nv_bfloat16 h = __float2bfloat16(v);
    __nv_bfloat16 l = __float2bfloat16(v - __bfloat162float(h));
    g_wbt_hi[e] = h;
    g_wbt_lo[e] = l;
}

// ---------------------------------------------------------------------------
// Preprocess: per point n compute agg[m*131+c], emit bf16 hi/lo splits
// ---------------------------------------------------------------------------
__global__ __launch_bounds__(256) void preprocess_kernel(
    const float* __restrict__ p,
    const float* __restrict__ x,
    const float* __restrict__ kp,
    const int*   __restrict__ idx)
{
    const int n   = blockIdx.x;
    const int tid = threadIdx.x;

    __shared__ float s_pj[KNB][3];
    __shared__ float s_l2[KNB];
    __shared__ float s_inv;
    __shared__ float s_corr[NKP][KNB];
    __shared__ float s_xj[KNB][CXJ + 1];
    __shared__ int   s_idx[KNB];

    if (tid < KNB) s_idx[tid] = idx[(size_t)n * KNB + tid];
    __syncthreads();

    const float px = p[3 * n + 0];
    const float py = p[3 * n + 1];
    const float pz = p[3 * n + 2];

    if (tid < KNB) {
        int j = s_idx[tid];
        float dx = p[3 * j + 0] - px;
        float dy = p[3 * j + 1] - py;
        float dz = p[3 * j + 2] - pz;
        s_pj[tid][0] = dx; s_pj[tid][1] = dy; s_pj[tid][2] = dz;
        s_l2[tid] = sqrtf(dx * dx + dy * dy + dz * dz);
    }
    __syncthreads();

    if (tid == 0) {
        float mx = s_l2[0];
        #pragma unroll
        for (int k = 1; k < KNB; k++) mx = fmaxf(mx, s_l2[k]);
        s_inv = 1.0f / (mx + 1e-10f);
    }
    __syncthreads();

    const float inv = s_inv;
    if (tid < KNB) {
        s_pj[tid][0] *= inv;
        s_pj[tid][1] *= inv;
        s_pj[tid][2] *= inv;
    }
    __syncthreads();

    const float INV_SCALE = (float)(1.0 / (0.3 * 0.3 * 2.0 + 1e-10));
    if (tid < NKP * KNB) {
        int m = tid / KNB;
        int k = tid - m * KNB;
        float dx = kp[m * 3 + 0] - s_pj[k][0];
        float dy = kp[m * 3 + 1] - s_pj[k][1];
        float dz = kp[m * 3 + 2] - s_pj[k][2];
        s_corr[m][k] = expf(-(dx * dx + dy * dy + dz * dz) * INV_SCALE);
    }

    for (int e = tid; e < KNB * CXJ; e += 256) {
        int k = e / CXJ;
        int c = e - k * CXJ;
        float v;
        if (c < 3) v = s_pj[k][c];
        else       v = x[(size_t)s_idx[k] * CIN + (c - 3)];
        s_xj[k][c] = v;
    }
    __syncthreads();

    __nv_bfloat16* dh = &g_agg_hi[(size_t)n * KP2];
    __nv_bfloat16* dl = &g_agg_lo[(size_t)n * KP2];
    for (int o = tid; o < KP2; o += 256) {
        float acc = 0.0f;
        if (o < KTOT) {
            int m = o / CXJ;
            int c = o - m * CXJ;
            #pragma unroll
            for (int k = 0; k < KNB; k++)
                acc = fmaf(s_corr[m][k], s_xj[k][c], acc);
        }
        __nv_bfloat16 h = __float2bfloat16(acc);
        __nv_bfloat16 l = __float2bfloat16(acc - __bfloat162float(h));
        dh[o] = h;
        dl[o] = l;
    }
}

// ---------------------------------------------------------------------------
// GEMM via mma.sync (bf16, 3-term split) + cp.async double-buffered pipeline
// CTA tile 128(M) x 256(N), K chunk 64, 8 warps (warp tile 64x64)
// ---------------------------------------------------------------------------
// smem layout per stage (bytes):
//   A_hi: 128 rows x (64+8) halves = 18432
//   A_lo: 18432
//   B_hi:  64 rows x (256+8) halves = 33792
//   B_lo: 33792
#define A_STRIDE 144u            // (64+8)*2 bytes
#define B_STRIDE 528u            // (256+8)*2 bytes
#define ASPL     18432u
#define BSPL     33792u
#define BOFF     36864u          // A_hi + A_lo
#define STG      104448u
#define SMEM_DYN (2u * STG)      // 208896

__global__ __launch_bounds__(256, 1) void gemm_mma_kernel(
    const float* __restrict__ conv_b,
    const float* __restrict__ bn_gamma,
    const float* __restrict__ bn_beta,
    const float* __restrict__ bn_mean,
    const float* __restrict__ bn_var,
    float* __restrict__ out)
{
    extern __shared__ __align__(1024) char smem[];
    __shared__ float s_sc[COUT];
    __shared__ float s_bi[COUT];

    const uint32_t sb   = smem_u32(smem);
    const int tid    = threadIdx.x;
    const int wid    = tid >> 5;
    const int lane   = tid & 31;
    const int warp_m = wid >> 2;          // 0..1
    const int warp_n = wid & 3;           // 0..3
    const int m0     = blockIdx.x * 128;

    // epilogue constants
    {
        int col = tid;
        float s = bn_gamma[col] * rsqrtf(bn_var[col] + 1e-5f);
        s_sc[col] = s;
        s_bi[col] = (conv_b[col] - bn_mean[col]) * s + bn_beta[col];
    }

    float acc[4][8][4];
    #pragma unroll
    for (int i = 0; i < 4; i++)
        #pragma unroll
        for (int j = 0; j < 8; j++)
            #pragma unroll
            for (int q = 0; q < 4; q++) acc[i][j][q] = 0.0f;

    // ---- chunk loader (cp.async) ----
    auto load_chunk = [&](int c, int stage) {
        const uint32_t base = sb + (uint32_t)stage * STG;
        // A: 128 rows x 8 segs x 2 splits = 2048 16B txns
        #pragma unroll
        for (int L = 0; L < 8; L++) {
            int v     = tid + L * 256;           // 0..2047
            int split = v >> 10;
            int rem   = v & 1023;
            int row   = rem >> 3;
            int seg   = rem & 7;
            int gr    = m0 + row;
            uint32_t ok = (gr < N_PTS) ? 16u : 0u;
            int grc   = (gr < N_PTS) ? gr : 0;
            const __nv_bfloat16* src =
                (split == 0 ? g_agg_hi : g_agg_lo) +
                (size_t)grc * KP2 + (size_t)c * 64 + seg * 8;
            uint32_t dst = base + (uint32_t)split * ASPL +
                           (uint32_t)row * A_STRIDE + (uint32_t)seg * 16u;
            cp_async16(dst, src, ok);
        }
        // B: 64 rows x 32 segs x 2 splits = 4096 16B txns
        #pragma unroll
        for (int L = 0; L < 16; L++) {
            int v     = tid + L * 256;           // 0..4095
            int split = v >> 11;
            int rem   = v & 2047;
            int krow  = rem >> 5;
            int seg   = rem & 31;
            const __nv_bfloat16* src =
                (split == 0 ? g_wbt_hi : g_wbt_lo) +
                (size_t)(c * 64 + krow) * COUT + seg * 8;
            uint32_t dst = base + BOFF + (uint32_t)split * BSPL +
                           (uint32_t)krow * B_STRIDE + (uint32_t)seg * 16u;
            cp_async16(dst, src, 16u);
        }
        cp_commit();
    };

    // per-lane ldmatrix base offsets
    const uint32_t a_base = (uint32_t)(warp_m * 64 + (lane & 15)) * A_STRIDE +
                            (uint32_t)(lane >> 4) * 16u;
    const uint32_t b_base = (uint32_t)(lane & 15) * B_STRIDE + BOFF +
                            (uint32_t)(warp_n * 64 + (lane >> 4) * 8) * 2u;

    load_chunk(0, 0);

    for (int c = 0; c < NCHUNK; c++) {
        const int st = c & 1;
        if (c + 1 < NCHUNK) {
            load_chunk(c + 1, (c + 1) & 1);
            cp_wait<1>();
        } else {
            cp_wait<0>();
        }
        __syncthreads();

        const uint32_t stg = sb + (uint32_t)st * STG;

        #pragma unroll
        for (int ks = 0; ks < 4; ks++) {
            uint32_t ah[4][4], al[4][4];
            #pragma unroll
            for (int mi = 0; mi < 4; mi++) {
                uint32_t aa = stg + a_base + (uint32_t)(mi * 16) * A_STRIDE +
                              (uint32_t)ks * 32u;
                ldsm_x4(ah[mi], aa);
                ldsm_x4(al[mi], aa + ASPL);
            }
            uint32_t bh[8][2], bl[8][2];
            #pragma unroll
            for (int nb = 0; nb < 4; nb++) {
                uint32_t ba = stg + b_base + (uint32_t)(ks * 16) * B_STRIDE +
                              (uint32_t)nb * 32u;
                uint32_t t[4];
                ldsm_x4_t(t, ba);
                bh[2*nb][0] = t[0]; bh[2*nb][1] = t[1];
                bh[2*nb+1][0] = t[2]; bh[2*nb+1][1] = t[3];
                ldsm_x4_t(t, ba + BSPL);
                bl[2*nb][0] = t[0]; bl[2*nb][1] = t[1];
                bl[2*nb+1][0] = t[2]; bl[2*nb+1][1] = t[3];
            }
            #pragma unroll
            for (int mi = 0; mi < 4; mi++)
                #pragma unroll
                for (int ni = 0; ni < 8; ni++) {
                    mma_bf16(acc[mi][ni], ah[mi], bh[ni]);
                    mma_bf16(acc[mi][ni], ah[mi], bl[ni]);
                    mma_bf16(acc[mi][ni], al[mi], bh[ni]);
                }
        }
        __syncthreads();
    }

    // ---- epilogue: bias + BN + ReLU, float2 stores ----
    const int r_base = m0 + warp_m * 64;
    #pragma unroll
    for (int mi = 0; mi < 4; mi++) {
        #pragma unroll
        for (int h = 0; h < 2; h++) {
            int row = r_base + mi * 16 + (lane >> 2) + h * 8;
            if (row < N_PTS) {
                float* op = out + (size_t)row * COUT;
                #pragma unroll
                for (int ni = 0; ni < 8; ni++) {
                    int col = warp_n * 64 + ni * 8 + (lane & 3) * 2;
                    float2 v;
                    v.x = fmaxf(fmaf(acc[mi][ni][h*2+0], s_sc[col],   s_bi[col]),   0.0f);
                    v.y = fmaxf(fmaf(acc[mi][ni][h*2+1], s_sc[col+1], s_bi[col+1]), 0.0f);
                    *(float2*)(op + col) = v;
                }
            }
        }
    }
}

// ---------------------------------------------------------------------------
extern "C" void kernel_launch(void* const* d_in, const int* in_sizes, int n_in,
                              void* d_out, int out_size) {
    const float* p     = (const float*)d_in[0];
    const float* x     = (const float*)d_in[1];
    const float* kp    = (const float*)d_in[2];
    const float* w     = (const float*)d_in[3];
    const float* b     = (const float*)d_in[4];
    const float* gamma = (const float*)d_in[5];
    const float* beta  = (const float*)d_in[6];
    const float* mean  = (const float*)d_in[7];
    const float* var   = (const float*)d_in[8];
    const int*   idx   = (const int*)d_in[9];
    float* out = (float*)d_out;

    cudaFuncSetAttribute(gemm_mma_kernel,
                         cudaFuncAttributeMaxDynamicSharedMemorySize, SMEM_DYN);

    wt_split_kernel<<<(KP2 * COUT + 255) / 256, 256>>>(w);
    preprocess_kernel<<<N_PTS, 256>>>(p, x, kp, idx);
    gemm_mma_kernel<<<(N_PTS + 127) / 128, 256, SMEM_DYN>>>(
        b, gamma, beta, mean, var, out);
}

// round 6
// speedup vs baseline: 2.2932x; 1.1777x over previous
#include <cuda_runtime.h>
#include <cuda_fp16.h>
#include <cstdint>
#include <math.h>

#define N_PTS 100000
#define KNB   16
#define CIN   128
#define COUT  256
#define NKP   15
#define CXJ   131            // CIN + 3
#define KTOT  1965           // NKP * CXJ
#define KP2   1984           // padded: 31 * 64
#define NCHUNK 31            // K chunks of 64

// ---------------- scratch (allocation-free rule: __device__ globals) --------
__device__ __align__(128) __half g_agg[(size_t)N_PTS * KP2];          // fp16 A
__device__ __align__(128) __half g_wbt_hi[(size_t)KP2 * COUT];        // [k][n]
__device__ __align__(128) __half g_wbt_lo[(size_t)KP2 * COUT];        // [k][n]

// ---------------- PTX helpers (sm_103 base target only) ---------------------
__device__ __forceinline__ uint32_t smem_u32(const void* p) {
    uint32_t a;
    asm("{ .reg .u64 t; cvta.to.shared.u64 t, %1; cvt.u32.u64 %0, t; }"
        : "=r"(a) : "l"(p));
    return a;
}

__device__ __forceinline__ void cp_async16(uint32_t dst, const void* src,
                                           uint32_t srcsize) {
    asm volatile("cp.async.cg.shared.global [%0], [%1], 16, %2;"
                 :: "r"(dst), "l"(src), "r"(srcsize) : "memory");
}

__device__ __forceinline__ void cp_commit() {
    asm volatile("cp.async.commit_group;" ::: "memory");
}

template <int N>
__device__ __forceinline__ void cp_wait() {
    asm volatile("cp.async.wait_group %0;" :: "n"(N) : "memory");
}

__device__ __forceinline__ void ldsm_x4(uint32_t* r, uint32_t addr) {
    asm volatile("ldmatrix.sync.aligned.m8n8.x4.shared.b16 {%0,%1,%2,%3}, [%4];"
                 : "=r"(r[0]), "=r"(r[1]), "=r"(r[2]), "=r"(r[3]) : "r"(addr));
}

__device__ __forceinline__ void ldsm_x4_t(uint32_t* r, uint32_t addr) {
    asm volatile("ldmatrix.sync.aligned.m8n8.x4.trans.shared.b16 {%0,%1,%2,%3}, [%4];"
                 : "=r"(r[0]), "=r"(r[1]), "=r"(r[2]), "=r"(r[3]) : "r"(addr));
}

__device__ __forceinline__ void mma_fp16(float* c, const uint32_t* a,
                                         const uint32_t* b) {
    asm volatile(
        "mma.sync.aligned.m16n8k16.row.col.f32.f16.f16.f32 "
        "{%0,%1,%2,%3}, {%4,%5,%6,%7}, {%8,%9}, {%0,%1,%2,%3};"
        : "+f"(c[0]), "+f"(c[1]), "+f"(c[2]), "+f"(c[3])
        : "r"(a[0]), "r"(a[1]), "r"(a[2]), "r"(a[3]), "r"(b[0]), "r"(b[1]));
}

// ---------------------------------------------------------------------------
// Weight prep: g_wbt[k][n] = split_fp16(conv_w[n][k%131][k/131]); pad -> 0
// ---------------------------------------------------------------------------
__global__ void wt_split_kernel(const float* __restrict__ conv_w) {
    int e = blockIdx.x * blockDim.x + threadIdx.x;
    if (e >= KP2 * COUT) return;
    int k = e / COUT;
    int n = e - k * COUT;
    float v = 0.0f;
    if (k < KTOT) {
        int m = k / CXJ;
        int c = k - m * CXJ;
        v = conv_w[((size_t)n * CXJ + c) * NKP + m];
    }
    __half h = __float2half_rn(v);
    __half l = __float2half_rn(v - __half2float(h));
    g_wbt_hi[e] = h;
    g_wbt_lo[e] = l;
}

// ---------------------------------------------------------------------------
// Preprocess: register-tiled outer product, single fp16 output
// Block = 1 point, 256 threads.
// ---------------------------------------------------------------------------
__global__ __launch_bounds__(256) void preprocess_kernel(
    const float* __restrict__ p,
    const float* __restrict__ x,
    const float* __restrict__ kp,
    const int*   __restrict__ idx)
{
    const int n   = blockIdx.x;
    const int tid = threadIdx.x;

    // NOTE: every vector-accessed shared array MUST be explicitly 16B aligned
    // (a stray 4B scalar between arrays shifted bases to %16==4 in R4/R5 and
    //  LDS.128 trapped with "misaligned address").
    __shared__ __align__(16) float s_x[KNB][CIN];     // 8 KB, float4-accessed
    __shared__ __align__(16) float s_agg[KP2];        // 7.75 KB, float4-accessed
    __shared__ __align__(16) float s_pjn[KNB][3];
    __shared__ __align__(16) float s_corr[NKP][KNB];
    __shared__ __align__(16) float s_l2[KNB];
    __shared__ __align__(16) int   s_idx[KNB];
    __shared__ float s_inv;                           // scalar last

    if (tid < KNB) s_idx[tid] = idx[(size_t)n * KNB + tid];
    if (tid < KP2 - KTOT) s_agg[KTOT + tid] = 0.0f;   // zero pad region
    __syncthreads();

    // gather x rows into smem (coalesced float4)
    {
        int r = tid >> 4;          // 0..15
        int q = tid & 15;          // 0..15
        const float4* src = (const float4*)(x + (size_t)s_idx[r] * CIN);
        float4 v0 = src[q * 2 + 0];
        float4 v1 = src[q * 2 + 1];
        *(float4*)&s_x[r][q * 8 + 0] = v0;
        *(float4*)&s_x[r][q * 8 + 4] = v1;
    }

    const float px = p[3 * n + 0];
    const float py = p[3 * n + 1];
    const float pz = p[3 * n + 2];

    if (tid < KNB) {
        int j = s_idx[tid];
        float dx = p[3 * j + 0] - px;
        float dy = p[3 * j + 1] - py;
        float dz = p[3 * j + 2] - pz;
        s_pjn[tid][0] = dx; s_pjn[tid][1] = dy; s_pjn[tid][2] = dz;
        s_l2[tid] = sqrtf(dx * dx + dy * dy + dz * dz);
    }
    __syncthreads();

    if (tid == 0) {
        float mx = s_l2[0];
        #pragma unroll
        for (int k = 1; k < KNB; k++) mx = fmaxf(mx, s_l2[k]);
        s_inv = 1.0f / (mx + 1e-10f);
    }
    __syncthreads();

    if (tid < KNB) {
        float inv = s_inv;
        s_pjn[tid][0] *= inv;
        s_pjn[tid][1] *= inv;
        s_pjn[tid][2] *= inv;
    }
    __syncthreads();

    const float INV_SCALE = (float)(1.0 / (0.3 * 0.3 * 2.0 + 1e-10));
    if (tid < NKP * KNB) {
        int m = tid >> 4;
        int k = tid & 15;
        float dx = kp[m * 3 + 0] - s_pjn[k][0];
        float dy = kp[m * 3 + 1] - s_pjn[k][1];
        float dz = kp[m * 3 + 2] - s_pjn[k][2];
        s_corr[m][k] = expf(-(dx * dx + dy * dy + dz * dz) * INV_SCALE);
    }
    __syncthreads();

    // ---- register-tiled agg: thread(m,j) owns cols [3+8j, 3+8j+8) of row m
    if (tid < NKP * 16) {
        const int m = tid >> 4;
        const int j = tid & 15;
        float cm[KNB];
        #pragma unroll
        for (int k = 0; k < KNB; k++) cm[k] = s_corr[m][k];
        float a[8] = {0,0,0,0,0,0,0,0};
        #pragma unroll
        for (int k = 0; k < KNB; k++) {
            float4 v0 = *(const float4*)&s_x[k][8 * j + 0];
            float4 v1 = *(const float4*)&s_x[k][8 * j + 4];
            float c = cm[k];
            a[0] = fmaf(c, v0.x, a[0]); a[1] = fmaf(c, v0.y, a[1]);
            a[2] = fmaf(c, v0.z, a[2]); a[3] = fmaf(c, v0.w, a[3]);
            a[4] = fmaf(c, v1.x, a[4]); a[5] = fmaf(c, v1.y, a[5]);
            a[6] = fmaf(c, v1.z, a[6]); a[7] = fmaf(c, v1.w, a[7]);
        }
        float* dst = &s_agg[m * CXJ + 3 + 8 * j];
        #pragma unroll
        for (int i = 0; i < 8; i++) dst[i] = a[i];   // scalar stores (unaligned col ok)
    } else if (tid >= 240 && tid < 240 + NKP) {
        // pj columns (c = 0,1,2) for row m
        const int m = tid - 240;
        float a0 = 0, a1 = 0, a2 = 0;
        #pragma unroll
        for (int k = 0; k < KNB; k++) {
            float c = s_corr[m][k];
            a0 = fmaf(c, s_pjn[k][0], a0);
            a1 = fmaf(c, s_pjn[k][1], a1);
            a2 = fmaf(c, s_pjn[k][2], a2);
        }
        s_agg[m * CXJ + 0] = a0;
        s_agg[m * CXJ + 1] = a1;
        s_agg[m * CXJ + 2] = a2;
    }
    __syncthreads();

    // ---- coalesced fp16 store: thread t writes halves [8t, 8t+8)
    if (tid < KP2 / 8) {
        float4 f0 = ((const float4*)s_agg)[2 * tid + 0];
        float4 f1 = ((const float4*)s_agg)[2 * tid + 1];
        union { uint4 u; __half h[8]; } pk;      // 16B-aligned pack
        pk.h[0] = __float2half_rn(f0.x); pk.h[1] = __float2half_rn(f0.y);
        pk.h[2] = __float2half_rn(f0.z); pk.h[3] = __float2half_rn(f0.w);
        pk.h[4] = __float2half_rn(f1.x); pk.h[5] = __float2half_rn(f1.y);
        pk.h[6] = __float2half_rn(f1.z); pk.h[7] = __float2half_rn(f1.w);
        *(uint4*)(g_agg + (size_t)n * KP2 + 8 * tid) = pk.u;
    }
}

// ---------------------------------------------------------------------------
// GEMM via mma.sync fp16 (2-term: A*Whi + A*Wlo) + cp.async double buffer
// CTA tile 128(M) x 256(N), K chunk 64, 8 warps (warp tile 64x64)
// ---------------------------------------------------------------------------
#define A_STRIDE 144u            // (64+8)*2 bytes
#define B_STRIDE 528u            // (256+8)*2 bytes
#define ASPL     18432u          // A tile bytes
#define BSPL     33792u          // one B split
#define BOFF     18432u          // B starts after A
#define STG      86016u          // A + B_hi + B_lo
#define SMEM_DYN (2u * STG)      // 172032

__global__ __launch_bounds__(256, 1) void gemm_mma_kernel(
    const float* __restrict__ conv_b,
    const float* __restrict__ bn_gamma,
    const float* __restrict__ bn_beta,
    const float* __restrict__ bn_mean,
    const float* __restrict__ bn_var,
    float* __restrict__ out)
{
    extern __shared__ __align__(1024) char smem[];
    __shared__ __align__(16) float s_sc[COUT];
    __shared__ __align__(16) float s_bi[COUT];

    const uint32_t sb   = smem_u32(smem);
    const int tid    = threadIdx.x;
    const int wid    = tid >> 5;
    const int lane   = tid & 31;
    const int warp_m = wid >> 2;          // 0..1
    const int warp_n = wid & 3;           // 0..3
    const int m0     = blockIdx.x * 128;

    {
        int col = tid;
        float s = bn_gamma[col] * rsqrtf(bn_var[col] + 1e-5f);
        s_sc[col] = s;
        s_bi[col] = (conv_b[col] - bn_mean[col]) * s + bn_beta[col];
    }

    float acc[4][8][4];
    #pragma unroll
    for (int i = 0; i < 4; i++)
        #pragma unroll
        for (int j = 0; j < 8; j++)
            #pragma unroll
            for (int q = 0; q < 4; q++) acc[i][j][q] = 0.0f;

    auto load_chunk = [&](int c, int stage) {
        const uint32_t base = sb + (uint32_t)stage * STG;
        // A: 128 rows x 8 segs (16B) = 1024 txns
        #pragma unroll
        for (int L = 0; L < 4; L++) {
            int v   = tid + L * 256;             // 0..1023
            int row = v >> 3;
            int seg = v & 7;
            int gr  = m0 + row;
            uint32_t ok = (gr < N_PTS) ? 16u : 0u;
            int grc = (gr < N_PTS) ? gr : 0;
            const __half* src = g_agg + (size_t)grc * KP2 + (size_t)c * 64 + seg * 8;
            uint32_t dst = base + (uint32_t)row * A_STRIDE + (uint32_t)seg * 16u;
            cp_async16(dst, src, ok);
        }
        // B: 2 splits x 64 rows x 32 segs = 4096 txns
        #pragma unroll
        for (int L = 0; L < 16; L++) {
            int v     = tid + L * 256;           // 0..4095
            int split = v >> 11;
            int rem   = v & 2047;
            int krow  = rem >> 5;
            int seg   = rem & 31;
            const __half* src =
                (split == 0 ? g_wbt_hi : g_wbt_lo) +
                (size_t)(c * 64 + krow) * COUT + seg * 8;
            uint32_t dst = base + BOFF + (uint32_t)split * BSPL +
                           (uint32_t)krow * B_STRIDE + (uint32_t)seg * 16u;
            cp_async16(dst, src, 16u);
        }
        cp_commit();
    };

    const uint32_t a_base = (uint32_t)(warp_m * 64 + (lane & 15)) * A_STRIDE +
                            (uint32_t)(lane >> 4) * 16u;
    const uint32_t b_base = (uint32_t)(lane & 15) * B_STRIDE + BOFF +
                            (uint32_t)(warp_n * 64 + (lane >> 4) * 8) * 2u;

    load_chunk(0, 0);

    for (int c = 0; c < NCHUNK; c++) {
        const int st = c & 1;
        if (c + 1 < NCHUNK) {
            load_chunk(c + 1, (c + 1) & 1);
            cp_wait<1>();
        } else {
            cp_wait<0>();
        }
        __syncthreads();

        const uint32_t stg = sb + (uint32_t)st * STG;

        #pragma unroll
        for (int ks = 0; ks < 4; ks++) {
            uint32_t ah[4][4];
            #pragma unroll
            for (int mi = 0; mi < 4; mi++) {
                uint32_t aa = stg + a_base + (uint32_t)(mi * 16) * A_STRIDE +
                              (uint32_t)ks * 32u;
                ldsm_x4(ah[mi], aa);
            }
            uint32_t bh[8][2], bl[8][2];
            #pragma unroll
            for (int nb = 0; nb < 4; nb++) {
                uint32_t ba = stg + b_base + (uint32_t)(ks * 16) * B_STRIDE +
                              (uint32_t)nb * 32u;
                uint32_t t[4];
                ldsm_x4_t(t, ba);
                bh[2*nb][0] = t[0]; bh[2*nb][1] = t[1];
                bh[2*nb+1][0] = t[2]; bh[2*nb+1][1] = t[3];
                ldsm_x4_t(t, ba + BSPL);
                bl[2*nb][0] = t[0]; bl[2*nb][1] = t[1];
                bl[2*nb+1][0] = t[2]; bl[2*nb+1][1] = t[3];
            }
            #pragma unroll
            for (int mi = 0; mi < 4; mi++)
                #pragma unroll
                for (int ni = 0; ni < 8; ni++) {
                    mma_fp16(acc[mi][ni], ah[mi], bh[ni]);
                    mma_fp16(acc[mi][ni], ah[mi], bl[ni]);
                }
        }
        __syncthreads();
    }

    // ---- epilogue: bias + BN + ReLU, float2 stores ----
    const int r_base = m0 + warp_m * 64;
    #pragma unroll
    for (int mi = 0; mi < 4; mi++) {
        #pragma unroll
        for (int h = 0; h < 2; h++) {
            int row = r_base + mi * 16 + (lane >> 2) + h * 8;
            if (row < N_PTS) {
                float* op = out + (size_t)row * COUT;
                #pragma unroll
                for (int ni = 0; ni < 8; ni++) {
                    int col = warp_n * 64 + ni * 8 + (lane & 3) * 2;
                    float2 v;
                    v.x = fmaxf(fmaf(acc[mi][ni][h*2+0], s_sc[col],   s_bi[col]),   0.0f);
                    v.y = fmaxf(fmaf(acc[mi][ni][h*2+1], s_sc[col+1], s_bi[col+1]), 0.0f);
                    *(float2*)(op + col) = v;
                }
            }
        }
    }
}

// ---------------------------------------------------------------------------
extern "C" void kernel_launch(void* const* d_in, const int* in_sizes, int n_in,
                              void* d_out, int out_size) {
    const float* p     = (const float*)d_in[0];
    const float* x     = (const float*)d_in[1];
    const float* kp    = (const float*)d_in[2];
    const float* w     = (const float*)d_in[3];
    const float* b     = (const float*)d_in[4];
    const float* gamma = (const float*)d_in[5];
    const float* beta  = (const float*)d_in[6];
    const float* mean  = (const float*)d_in[7];
    const float* var   = (const float*)d_in[8];
    const int*   idx   = (const int*)d_in[9];
    float* out = (float*)d_out;

    cudaFuncSetAttribute(gemm_mma_kernel,
                         cudaFuncAttributeMaxDynamicSharedMemorySize, SMEM_DYN);

    wt_split_kernel<<<(KP2 * COUT + 255) / 256, 256>>>(w);
    preprocess_kernel<<<N_PTS, 256>>>(p, x, kp, idx);
    gemm_mma_kernel<<<(N_PTS + 127) / 128, 256, SMEM_DYN>>>(
        b, gamma, beta, mean, var, out);
}

// round 7
// speedup vs baseline: 2.6122x; 1.1391x over previous
#include <cuda_runtime.h>
#include <cuda_fp16.h>
#include <cstdint>
#include <math.h>

#define N_PTS 100000
#define KNB   16
#define CIN   128
#define COUT  256
#define NKP   15
#define CXJ   131            // CIN + 3
#define KTOT  1965           // NKP * CXJ
#define KP2   1984           // padded: 31 * 64
#define NCHUNK 31            // K chunks of 64

// ---------------- scratch (allocation-free rule: __device__ globals) --------
__device__ __align__(128) __half g_agg[(size_t)N_PTS * KP2];          // fp16 A
__device__ __align__(128) __half g_wbt[(size_t)KP2 * COUT];           // [k][n] fp16

// ---------------- PTX helpers (sm_103 base target only) ---------------------
__device__ __forceinline__ uint32_t smem_u32(const void* p) {
    uint32_t a;
    asm("{ .reg .u64 t; cvta.to.shared.u64 t, %1; cvt.u32.u64 %0, t; }"
        : "=r"(a) : "l"(p));
    return a;
}

__device__ __forceinline__ void cp_async16(uint32_t dst, const void* src,
                                           uint32_t srcsize) {
    asm volatile("cp.async.cg.shared.global [%0], [%1], 16, %2;"
                 :: "r"(dst), "l"(src), "r"(srcsize) : "memory");
}

__device__ __forceinline__ void cp_commit() {
    asm volatile("cp.async.commit_group;" ::: "memory");
}

template <int N>
__device__ __forceinline__ void cp_wait() {
    asm volatile("cp.async.wait_group %0;" :: "n"(N) : "memory");
}

__device__ __forceinline__ void ldsm_x4(uint32_t* r, uint32_t addr) {
    asm volatile("ldmatrix.sync.aligned.m8n8.x4.shared.b16 {%0,%1,%2,%3}, [%4];"
                 : "=r"(r[0]), "=r"(r[1]), "=r"(r[2]), "=r"(r[3]) : "r"(addr));
}

__device__ __forceinline__ void ldsm_x4_t(uint32_t* r, uint32_t addr) {
    asm volatile("ldmatrix.sync.aligned.m8n8.x4.trans.shared.b16 {%0,%1,%2,%3}, [%4];"
                 : "=r"(r[0]), "=r"(r[1]), "=r"(r[2]), "=r"(r[3]) : "r"(addr));
}

__device__ __forceinline__ void mma_fp16(float* c, const uint32_t* a,
                                         const uint32_t* b) {
    asm volatile(
        "mma.sync.aligned.m16n8k16.row.col.f32.f16.f16.f32 "
        "{%0,%1,%2,%3}, {%4,%5,%6,%7}, {%8,%9}, {%0,%1,%2,%3};"
        : "+f"(c[0]), "+f"(c[1]), "+f"(c[2]), "+f"(c[3])
        : "r"(a[0]), "r"(a[1]), "r"(a[2]), "r"(a[3]), "r"(b[0]), "r"(b[1]));
}

// ---------------------------------------------------------------------------
// Weight prep: g_wbt[k][n] = fp16(conv_w[n][k%131][k/131]); pad -> 0
// ---------------------------------------------------------------------------
__global__ void wt_split_kernel(const float* __restrict__ conv_w) {
    int e = blockIdx.x * blockDim.x + threadIdx.x;
    if (e >= KP2 * COUT) return;
    int k = e / COUT;
    int n = e - k * COUT;
    float v = 0.0f;
    if (k < KTOT) {
        int m = k / CXJ;
        int c = k - m * CXJ;
        v = conv_w[((size_t)n * CXJ + c) * NKP + m];
    }
    g_wbt[e] = __float2half_rn(v);
}

// ---------------------------------------------------------------------------
// Preprocess: register-tiled outer product, single fp16 output
// Block = 1 point, 256 threads.
// ---------------------------------------------------------------------------
__global__ __launch_bounds__(256) void preprocess_kernel(
    const float* __restrict__ p,
    const float* __restrict__ x,
    const float* __restrict__ kp,
    const int*   __restrict__ idx)
{
    const int n   = blockIdx.x;
    const int tid = threadIdx.x;

    // every vector-accessed shared array explicitly 16B aligned (R5 lesson)
    __shared__ __align__(16) float s_x[KNB][CIN];     // 8 KB, float4-accessed
    __shared__ __align__(16) float s_agg[KP2];        // 7.75 KB, float4-accessed
    __shared__ __align__(16) float s_pjn[KNB][3];
    __shared__ __align__(16) float s_corr[NKP][KNB];
    __shared__ __align__(16) float s_l2[KNB];
    __shared__ __align__(16) int   s_idx[KNB];
    __shared__ float s_inv;                           // scalar last

    if (tid < KNB) s_idx[tid] = idx[(size_t)n * KNB + tid];
    if (tid < KP2 - KTOT) s_agg[KTOT + tid] = 0.0f;   // zero pad region
    __syncthreads();

    // gather x rows into smem (coalesced float4)
    {
        int r = tid >> 4;          // 0..15
        int q = tid & 15;          // 0..15
        const float4* src = (const float4*)(x + (size_t)s_idx[r] * CIN);
        float4 v0 = src[q * 2 + 0];
        float4 v1 = src[q * 2 + 1];
        *(float4*)&s_x[r][q * 8 + 0] = v0;
        *(float4*)&s_x[r][q * 8 + 4] = v1;
    }

    const float px = p[3 * n + 0];
    const float py = p[3 * n + 1];
    const float pz = p[3 * n + 2];

    if (tid < KNB) {
        int j = s_idx[tid];
        float dx = p[3 * j + 0] - px;
        float dy = p[3 * j + 1] - py;
        float dz = p[3 * j + 2] - pz;
        s_pjn[tid][0] = dx; s_pjn[tid][1] = dy; s_pjn[tid][2] = dz;
        s_l2[tid] = sqrtf(dx * dx + dy * dy + dz * dz);
    }
    __syncthreads();

    if (tid == 0) {
        float mx = s_l2[0];
        #pragma unroll
        for (int k = 1; k < KNB; k++) mx = fmaxf(mx, s_l2[k]);
        s_inv = 1.0f / (mx + 1e-10f);
    }
    __syncthreads();

    if (tid < KNB) {
        float inv = s_inv;
        s_pjn[tid][0] *= inv;
        s_pjn[tid][1] *= inv;
        s_pjn[tid][2] *= inv;
    }
    __syncthreads();

    const float INV_SCALE = (float)(1.0 / (0.3 * 0.3 * 2.0 + 1e-10));
    if (tid < NKP * KNB) {
        int m = tid >> 4;
        int k = tid & 15;
        float dx = kp[m * 3 + 0] - s_pjn[k][0];
        float dy = kp[m * 3 + 1] - s_pjn[k][1];
        float dz = kp[m * 3 + 2] - s_pjn[k][2];
        s_corr[m][k] = expf(-(dx * dx + dy * dy + dz * dz) * INV_SCALE);
    }
    __syncthreads();

    // ---- register-tiled agg: thread(m,j) owns cols [3+8j, 3+8j+8) of row m
    if (tid < NKP * 16) {
        const int m = tid >> 4;
        const int j = tid & 15;
        float cm[KNB];
        #pragma unroll
        for (int k = 0; k < KNB; k++) cm[k] = s_corr[m][k];
        float a[8] = {0,0,0,0,0,0,0,0};
        #pragma unroll
        for (int k = 0; k < KNB; k++) {
            float4 v0 = *(const float4*)&s_x[k][8 * j + 0];
            float4 v1 = *(const float4*)&s_x[k][8 * j + 4];
            float c = cm[k];
            a[0] = fmaf(c, v0.x, a[0]); a[1] = fmaf(c, v0.y, a[1]);
            a[2] = fmaf(c, v0.z, a[2]); a[3] = fmaf(c, v0.w, a[3]);
            a[4] = fmaf(c, v1.x, a[4]); a[5] = fmaf(c, v1.y, a[5]);
            a[6] = fmaf(c, v1.z, a[6]); a[7] = fmaf(c, v1.w, a[7]);
        }
        float* dst = &s_agg[m * CXJ + 3 + 8 * j];
        #pragma unroll
        for (int i = 0; i < 8; i++) dst[i] = a[i];
    } else if (tid >= 240 && tid < 240 + NKP) {
        const int m = tid - 240;
        float a0 = 0, a1 = 0, a2 = 0;
        #pragma unroll
        for (int k = 0; k < KNB; k++) {
            float c = s_corr[m][k];
            a0 = fmaf(c, s_pjn[k][0], a0);
            a1 = fmaf(c, s_pjn[k][1], a1);
            a2 = fmaf(c, s_pjn[k][2], a2);
        }
        s_agg[m * CXJ + 0] = a0;
        s_agg[m * CXJ + 1] = a1;
        s_agg[m * CXJ + 2] = a2;
    }
    __syncthreads();

    // ---- coalesced fp16 store: thread t writes halves [8t, 8t+8)
    if (tid < KP2 / 8) {
        float4 f0 = ((const float4*)s_agg)[2 * tid + 0];
        float4 f1 = ((const float4*)s_agg)[2 * tid + 1];
        union { uint4 u; __half h[8]; } pk;
        pk.h[0] = __float2half_rn(f0.x); pk.h[1] = __float2half_rn(f0.y);
        pk.h[2] = __float2half_rn(f0.z); pk.h[3] = __float2half_rn(f0.w);
        pk.h[4] = __float2half_rn(f1.x); pk.h[5] = __float2half_rn(f1.y);
        pk.h[6] = __float2half_rn(f1.z); pk.h[7] = __float2half_rn(f1.w);
        *(uint4*)(g_agg + (size_t)n * KP2 + 8 * tid) = pk.u;
    }
}

// ---------------------------------------------------------------------------
// GEMM via mma.sync fp16 single-term + cp.async 3-stage pipeline
// CTA tile 128(M) x 256(N), K chunk 64, 8 warps (warp tile 64x64)
// ---------------------------------------------------------------------------
#define A_STRIDE 144u            // (64+8)*2 bytes
#define B_STRIDE 528u            // (256+8)*2 bytes
#define BOFF     18432u          // B starts after A
#define STG      52224u          // A (18432) + B (33792)
#define NSTAGE   3
#define SMEM_DYN (3u * STG)      // 156672

__global__ __launch_bounds__(256, 1) void gemm_mma_kernel(
    const float* __restrict__ conv_b,
    const float* __restrict__ bn_gamma,
    const float* __restrict__ bn_beta,
    const float* __restrict__ bn_mean,
    const float* __restrict__ bn_var,
    float* __restrict__ out)
{
    extern __shared__ __align__(1024) char smem[];
    __shared__ __align__(16) float s_sc[COUT];
    __shared__ __align__(16) float s_bi[COUT];

    const uint32_t sb   = smem_u32(smem);
    const int tid    = threadIdx.x;
    const int wid    = tid >> 5;
    const int lane   = tid & 31;
    const int warp_m = wid >> 2;          // 0..1
    const int warp_n = wid & 3;           // 0..3
    const int m0     = blockIdx.x * 128;

    {
        int col = tid;
        float s = bn_gamma[col] * rsqrtf(bn_var[col] + 1e-5f);
        s_sc[col] = s;
        s_bi[col] = (conv_b[col] - bn_mean[col]) * s + bn_beta[col];
    }

    float acc[4][8][4];
    #pragma unroll
    for (int i = 0; i < 4; i++)
        #pragma unroll
        for (int j = 0; j < 8; j++)
            #pragma unroll
            for (int q = 0; q < 4; q++) acc[i][j][q] = 0.0f;

    auto load_chunk = [&](int c, int stage) {
        const uint32_t base = sb + (uint32_t)stage * STG;
        // A: 128 rows x 8 segs (16B) = 1024 txns
        #pragma unroll
        for (int L = 0; L < 4; L++) {
            int v   = tid + L * 256;             // 0..1023
            int row = v >> 3;
            int seg = v & 7;
            int gr  = m0 + row;
            uint32_t ok = (gr < N_PTS) ? 16u : 0u;
            int grc = (gr < N_PTS) ? gr : 0;
            const __half* src = g_agg + (size_t)grc * KP2 + (size_t)c * 64 + seg * 8;
            uint32_t dst = base + (uint32_t)row * A_STRIDE + (uint32_t)seg * 16u;
            cp_async16(dst, src, ok);
        }
        // B: 64 rows x 32 segs = 2048 txns
        #pragma unroll
        for (int L = 0; L < 8; L++) {
            int v    = tid + L * 256;            // 0..2047
            int krow = v >> 5;
            int seg  = v & 31;
            const __half* src = g_wbt + (size_t)(c * 64 + krow) * COUT + seg * 8;
            uint32_t dst = base + BOFF +
                           (uint32_t)krow * B_STRIDE + (uint32_t)seg * 16u;
            cp_async16(dst, src, 16u);
        }
        cp_commit();
    };

    const uint32_t a_base = (uint32_t)(warp_m * 64 + (lane & 15)) * A_STRIDE +
                            (uint32_t)(lane >> 4) * 16u;
    const uint32_t b_base = (uint32_t)(lane & 15) * B_STRIDE + BOFF +
                            (uint32_t)(warp_n * 64 + (lane >> 4) * 8) * 2u;

    load_chunk(0, 0);
    load_chunk(1, 1);

    for (int c = 0; c < NCHUNK; c++) {
        if (c + 2 < NCHUNK) load_chunk(c + 2, (c + 2) % NSTAGE);
        else                cp_commit();         // keep group count uniform
        cp_wait<2>();                            // chunk c resident
        __syncthreads();

        const uint32_t stg = sb + (uint32_t)(c % NSTAGE) * STG;

        #pragma unroll
        for (int ks = 0; ks < 4; ks++) {
            uint32_t ah[4][4];
            #pragma unroll
            for (int mi = 0; mi < 4; mi++) {
                uint32_t aa = stg + a_base + (uint32_t)(mi * 16) * A_STRIDE +
                              (uint32_t)ks * 32u;
                ldsm_x4(ah[mi], aa);
            }
            uint32_t bh[8][2];
            #pragma unroll
            for (int nb = 0; nb < 4; nb++) {
                uint32_t ba = stg + b_base + (uint32_t)(ks * 16) * B_STRIDE +
                              (uint32_t)nb * 32u;
                uint32_t t[4];
                ldsm_x4_t(t, ba);
                bh[2*nb][0] = t[0]; bh[2*nb][1] = t[1];
                bh[2*nb+1][0] = t[2]; bh[2*nb+1][1] = t[3];
            }
            #pragma unroll
            for (int mi = 0; mi < 4; mi++)
                #pragma unroll
                for (int ni = 0; ni < 8; ni++)
                    mma_fp16(acc[mi][ni], ah[mi], bh[ni]);
        }
        __syncthreads();
    }

    // ---- epilogue: bias + BN + ReLU, float2 stores ----
    const int r_base = m0 + warp_m * 64;
    #pragma unroll
    for (int mi = 0; mi < 4; mi++) {
        #pragma unroll
        for (int h = 0; h < 2; h++) {
            int row = r_base + mi * 16 + (lane >> 2) + h * 8;
            if (row < N_PTS) {
                float* op = out + (size_t)row * COUT;
                #pragma unroll
                for (int ni = 0; ni < 8; ni++) {
                    int col = warp_n * 64 + ni * 8 + (lane & 3) * 2;
                    float2 v;
                    v.x = fmaxf(fmaf(acc[mi][ni][h*2+0], s_sc[col],   s_bi[col]),   0.0f);
                    v.y = fmaxf(fmaf(acc[mi][ni][h*2+1], s_sc[col+1], s_bi[col+1]), 0.0f);
                    *(float2*)(op + col) = v;
                }
            }
        }
    }
}

// ---------------------------------------------------------------------------
extern "C" void kernel_launch(void* const* d_in, const int* in_sizes, int n_in,
                              void* d_out, int out_size) {
    const float* p     = (const float*)d_in[0];
    const float* x     = (const float*)d_in[1];
    const float* kp    = (const float*)d_in[2];
    const float* w     = (const float*)d_in[3];
    const float* b     = (const float*)d_in[4];
    const float* gamma = (const float*)d_in[5];
    const float* beta  = (const float*)d_in[6];
    const float* mean  = (const float*)d_in[7];
    const float* var   = (const float*)d_in[8];
    const int*   idx   = (const int*)d_in[9];
    float* out = (float*)d_out;

    cudaFuncSetAttribute(gemm_mma_kernel,
                         cudaFuncAttributeMaxDynamicSharedMemorySize, SMEM_DYN);

    wt_split_kernel<<<(KP2 * COUT + 255) / 256, 256>>>(w);
    preprocess_kernel<<<N_PTS, 256>>>(p, x, kp, idx);
    gemm_mma_kernel<<<(N_PTS + 127) / 128, 256, SMEM_DYN>>>(
        b, gamma, beta, mean, var, out);
}

// round 8
// speedup vs baseline: 6.2533x; 2.3939x over previous
#include <cuda_runtime.h>
#include <cuda_fp16.h>
#include <cstdint>
#include <math.h>

#define N_PTS 100000
#define KNB   16
#define CIN   128
#define COUT  256
#define NKP   15
#define CXJ   131            // CIN + 3
#define MROW  132            // padded per-m row: x 0..127, pj 128..130, pad 131
#define KP2   1984           // 15*132 = 1980, padded to 31*64
#define NCHUNK 31            // K chunks of 64
#define PPB   8              // points per block (warp-per-point); 100000 = 8*12500

// ---------------- scratch (allocation-free rule: __device__ globals) --------
__device__ __align__(128) __half g_agg[(size_t)N_PTS * KP2];          // fp16 A
__device__ __align__(128) __half g_wbt[(size_t)KP2 * COUT];           // [k][n] fp16

// ---------------- PTX helpers (sm_103 base target only) ---------------------
__device__ __forceinline__ uint32_t smem_u32(const void* p) {
    uint32_t a;
    asm("{ .reg .u64 t; cvta.to.shared.u64 t, %1; cvt.u32.u64 %0, t; }"
        : "=r"(a) : "l"(p));
    return a;
}

__device__ __forceinline__ void cp_async16(uint32_t dst, const void* src,
                                           uint32_t srcsize) {
    asm volatile("cp.async.cg.shared.global [%0], [%1], 16, %2;"
                 :: "r"(dst), "l"(src), "r"(srcsize) : "memory");
}

__device__ __forceinline__ void cp_commit() {
    asm volatile("cp.async.commit_group;" ::: "memory");
}

template <int N>
__device__ __forceinline__ void cp_wait() {
    asm volatile("cp.async.wait_group %0;" :: "n"(N) : "memory");
}

__device__ __forceinline__ void ldsm_x4(uint32_t* r, uint32_t addr) {
    asm volatile("ldmatrix.sync.aligned.m8n8.x4.shared.b16 {%0,%1,%2,%3}, [%4];"
                 : "=r"(r[0]), "=r"(r[1]), "=r"(r[2]), "=r"(r[3]) : "r"(addr));
}

__device__ __forceinline__ void ldsm_x4_t(uint32_t* r, uint32_t addr) {
    asm volatile("ldmatrix.sync.aligned.m8n8.x4.trans.shared.b16 {%0,%1,%2,%3}, [%4];"
                 : "=r"(r[0]), "=r"(r[1]), "=r"(r[2]), "=r"(r[3]) : "r"(addr));
}

__device__ __forceinline__ void mma_fp16(float* c, const uint32_t* a,
                                         const uint32_t* b) {
    asm volatile(
        "mma.sync.aligned.m16n8k16.row.col.f32.f16.f16.f32 "
        "{%0,%1,%2,%3}, {%4,%5,%6,%7}, {%8,%9}, {%0,%1,%2,%3};"
        : "+f"(c[0]), "+f"(c[1]), "+f"(c[2]), "+f"(c[3])
        : "r"(a[0]), "r"(a[1]), "r"(a[2]), "r"(a[3]), "r"(b[0]), "r"(b[1]));
}

// ---------------------------------------------------------------------------
// Weight prep with the new K layout: col = m*132 + nc
//   nc 0..127  -> x channel (orig c = nc+3)
//   nc 128..130-> pj dim    (orig c = nc-128)
//   nc 131, col>=1980 -> 0
// ---------------------------------------------------------------------------
__global__ void wt_split_kernel(const float* __restrict__ conv_w) {
    int e = blockIdx.x * blockDim.x + threadIdx.x;
    if (e >= KP2 * COUT) return;
    int col = e / COUT;
    int n   = e - col * COUT;
    float v = 0.0f;
    if (col < NKP * MROW) {
        int m  = col / MROW;
        int nc = col - m * MROW;
        if (nc != 131) {
            int c = (nc < 128) ? (nc + 3) : (nc - 128);
            v = conv_w[((size_t)n * CXJ + c) * NKP + m];
        }
    }
    g_wbt[e] = __float2half_rn(v);
}

// ---------------------------------------------------------------------------
// Preprocess v3: warp-per-point. Lane q owns x cols [4q,4q+4); x kept in regs.
// ---------------------------------------------------------------------------
__global__ __launch_bounds__(256) void preprocess_kernel(
    const float* __restrict__ p,
    const float* __restrict__ x,
    const float* __restrict__ kp,
    const int*   __restrict__ idx)
{
    __shared__ __align__(16) float  s_corr[PPB][NKP][16];   // 7.5 KB
    __shared__ __align__(16) float4 s_pjn[PPB][KNB];        // 2 KB
    __shared__ __align__(16) __half s_stage[PPB][KP2];      // 31 KB

    const int wid  = threadIdx.x >> 5;
    const int lane = threadIdx.x & 31;
    const int n    = blockIdx.x * PPB + wid;   // grid exact: 12500*8 = 100000

    // ---- neighbor indices (lanes 0..15) ----
    int idxv = 0;
    if (lane < KNB) idxv = idx[(size_t)n * KNB + lane];

    // center point (uniform load, L1-cached)
    const float px = p[3 * n + 0];
    const float py = p[3 * n + 1];
    const float pz = p[3 * n + 2];

    float dx = 0.f, dy = 0.f, dz = 0.f, l2 = 0.f;
    if (lane < KNB) {
        dx = p[3 * idxv + 0] - px;
        dy = p[3 * idxv + 1] - py;
        dz = p[3 * idxv + 2] - pz;
        l2 = sqrtf(dx * dx + dy * dy + dz * dz);
    }
    // max over 16 lanes (xor-shuffle stays within the 16-group)
    float mx = l2;
    #pragma unroll
    for (int o = 8; o >= 1; o >>= 1)
        mx = fmaxf(mx, __shfl_xor_sync(0xFFFFFFFFu, mx, o));
    const float inv = 1.0f / (mx + 1e-10f);

    if (lane < KNB)
        s_pjn[wid][lane] = make_float4(dx * inv, dy * inv, dz * inv, 0.f);
    __syncwarp();

    // ---- corr[m][k] ----
    const float INV_SCALE = (float)(1.0 / (0.3 * 0.3 * 2.0 + 1e-10));
    #pragma unroll
    for (int e = lane; e < NKP * KNB; e += 32) {
        int m = e >> 4, k = e & 15;
        float4 pj = s_pjn[wid][k];
        float ax = kp[m * 3 + 0] - pj.x;
        float ay = kp[m * 3 + 1] - pj.y;
        float az = kp[m * 3 + 2] - pj.z;
        s_corr[wid][m][k] = expf(-(ax * ax + ay * ay + az * az) * INV_SCALE);
    }
    // zero pad: col m*132+131 (m=0..14) and cols 1980..1983
    if (lane < NKP)                s_stage[wid][lane * MROW + 131] = __ushort_as_half(0);
    else if (lane < NKP + 4)       s_stage[wid][1980 + lane - NKP] = __ushort_as_half(0);
    __syncwarp();

    // ---- gather x into registers: xr[k] = x[idx_k][4*lane .. 4*lane+3] ----
    float4 xr[KNB];
    #pragma unroll
    for (int k = 0; k < KNB; k++) {
        int j = __shfl_sync(0xFFFFFFFFu, idxv, k);
        xr[k] = *(const float4*)(x + (size_t)j * CIN + 4 * lane);
    }

    // ---- main agg loop: for each m, 64 FMA into float4 acc ----
    #pragma unroll 1
    for (int m = 0; m < NKP; m++) {
        const float4 c0 = *(const float4*)&s_corr[wid][m][0];
        const float4 c1 = *(const float4*)&s_corr[wid][m][4];
        const float4 c2 = *(const float4*)&s_corr[wid][m][8];
        const float4 c3 = *(const float4*)&s_corr[wid][m][12];
        float4 a = make_float4(0.f, 0.f, 0.f, 0.f);
        const float cf[16] = {c0.x,c0.y,c0.z,c0.w, c1.x,c1.y,c1.z,c1.w,
                              c2.x,c2.y,c2.z,c2.w, c3.x,c3.y,c3.z,c3.w};
        #pragma unroll
        for (int k = 0; k < KNB; k++) {
            a.x = fmaf(cf[k], xr[k].x, a.x);
            a.y = fmaf(cf[k], xr[k].y, a.y);
            a.z = fmaf(cf[k], xr[k].z, a.z);
            a.w = fmaf(cf[k], xr[k].w, a.w);
        }
        // store 4 halves (8 B, aligned: (m*132+4*lane)*2 = 264m + 8*lane)
        union { uint2 u; __half2 h[2]; } pk;
        pk.h[0] = __floats2half2_rn(a.x, a.y);
        pk.h[1] = __floats2half2_rn(a.z, a.w);
        *(uint2*)&s_stage[wid][m * MROW + 4 * lane] = pk.u;
    }

    // ---- pj aggregation: lane m (<15) computes cols m*132+128..130 ----
    if (lane < NKP) {
        float a0 = 0.f, a1 = 0.f, a2 = 0.f;
        #pragma unroll
        for (int k = 0; k < KNB; k++) {
            float c = s_corr[wid][lane][k];
            float4 pj = s_pjn[wid][k];
            a0 = fmaf(c, pj.x, a0);
            a1 = fmaf(c, pj.y, a1);
            a2 = fmaf(c, pj.z, a2);
        }
        s_stage[wid][lane * MROW + 128] = __float2half_rn(a0);
        s_stage[wid][lane * MROW + 129] = __float2half_rn(a1);
        s_stage[wid][lane * MROW + 130] = __float2half_rn(a2);
    }
    __syncwarp();

    // ---- write out 1984 halves = 248 uint4, coalesced ----
    __half* dst = g_agg + (size_t)n * KP2;
    #pragma unroll
    for (int i = lane; i < KP2 / 8; i += 32)
        *(uint4*)(dst + 8 * i) = *(const uint4*)&s_stage[wid][8 * i];
}

// ---------------------------------------------------------------------------
// GEMM via mma.sync fp16 single-term + cp.async 3-stage pipeline (as R7)
// CTA tile 128(M) x 256(N), K chunk 64, 8 warps (warp tile 64x64)
// ---------------------------------------------------------------------------
#define A_STRIDE 144u            // (64+8)*2 bytes
#define B_STRIDE 528u            // (256+8)*2 bytes
#define BOFF     18432u          // B starts after A
#define STG      52224u          // A (18432) + B (33792)
#define NSTAGE   3
#define SMEM_DYN (3u * STG)      // 156672

__global__ __launch_bounds__(256, 1) void gemm_mma_kernel(
    const float* __restrict__ conv_b,
    const float* __restrict__ bn_gamma,
    const float* __restrict__ bn_beta,
    const float* __restrict__ bn_mean,
    const float* __restrict__ bn_var,
    float* __restrict__ out)
{
    extern __shared__ __align__(1024) char smem[];
    __shared__ __align__(16) float s_sc[COUT];
    __shared__ __align__(16) float s_bi[COUT];

    const uint32_t sb   = smem_u32(smem);
    const int tid    = threadIdx.x;
    const int wid    = tid >> 5;
    const int lane   = tid & 31;
    const int warp_m = wid >> 2;          // 0..1
    const int warp_n = wid & 3;           // 0..3
    const int m0     = blockIdx.x * 128;

    {
        int col = tid;
        float s = bn_gamma[col] * rsqrtf(bn_var[col] + 1e-5f);
        s_sc[col] = s;
        s_bi[col] = (conv_b[col] - bn_mean[col]) * s + bn_beta[col];
    }

    float acc[4][8][4];
    #pragma unroll
    for (int i = 0; i < 4; i++)
        #pragma unroll
        for (int j = 0; j < 8; j++)
            #pragma unroll
            for (int q = 0; q < 4; q++) acc[i][j][q] = 0.0f;

    auto load_chunk = [&](int c, int stage) {
        const uint32_t base = sb + (uint32_t)stage * STG;
        #pragma unroll
        for (int L = 0; L < 4; L++) {
            int v   = tid + L * 256;             // 0..1023
            int row = v >> 3;
            int seg = v & 7;
            int gr  = m0 + row;
            uint32_t ok = (gr < N_PTS) ? 16u : 0u;
            int grc = (gr < N_PTS) ? gr : 0;
            const __half* src = g_agg + (size_t)grc * KP2 + (size_t)c * 64 + seg * 8;
            uint32_t dst = base + (uint32_t)row * A_STRIDE + (uint32_t)seg * 16u;
            cp_async16(dst, src, ok);
        }
        #pragma unroll
        for (int L = 0; L < 8; L++) {
            int v    = tid + L * 256;            // 0..2047
            int krow = v >> 5;
            int seg  = v & 31;
            const __half* src = g_wbt + (size_t)(c * 64 + krow) * COUT + seg * 8;
            uint32_t dst = base + BOFF +
                           (uint32_t)krow * B_STRIDE + (uint32_t)seg * 16u;
            cp_async16(dst, src, 16u);
        }
        cp_commit();
    };

    const uint32_t a_base = (uint32_t)(warp_m * 64 + (lane & 15)) * A_STRIDE +
                            (uint32_t)(lane >> 4) * 16u;
    const uint32_t b_base = (uint32_t)(lane & 15) * B_STRIDE + BOFF +
                            (uint32_t)(warp_n * 64 + (lane >> 4) * 8) * 2u;

    load_chunk(0, 0);
    load_chunk(1, 1);

    for (int c = 0; c < NCHUNK; c++) {
        if (c + 2 < NCHUNK) load_chunk(c + 2, (c + 2) % NSTAGE);
        else                cp_commit();
        cp_wait<2>();
        __syncthreads();

        const uint32_t stg = sb + (uint32_t)(c % NSTAGE) * STG;

        #pragma unroll
        for (int ks = 0; ks < 4; ks++) {
            uint32_t ah[4][4];
            #pragma unroll
            for (int mi = 0; mi < 4; mi++) {
                uint32_t aa = stg + a_base + (uint32_t)(mi * 16) * A_STRIDE +
                              (uint32_t)ks * 32u;
                ldsm_x4(ah[mi], aa);
            }
            uint32_t bh[8][2];
            #pragma unroll
            for (int nb = 0; nb < 4; nb++) {
                uint32_t ba = stg + b_base + (uint32_t)(ks * 16) * B_STRIDE +
                              (uint32_t)nb * 32u;
                uint32_t t[4];
                ldsm_x4_t(t, ba);
                bh[2*nb][0] = t[0]; bh[2*nb][1] = t[1];
                bh[2*nb+1][0] = t[2]; bh[2*nb+1][1] = t[3];
            }
            #pragma unroll
            for (int mi = 0; mi < 4; mi++)
                #pragma unroll
                for (int ni = 0; ni < 8; ni++)
                    mma_fp16(acc[mi][ni], ah[mi], bh[ni]);
        }
        __syncthreads();
    }

    const int r_base = m0 + warp_m * 64;
    #pragma unroll
    for (int mi = 0; mi < 4; mi++) {
        #pragma unroll
        for (int h = 0; h < 2; h++) {
            int row = r_base + mi * 16 + (lane >> 2) + h * 8;
            if (row < N_PTS) {
                float* op = out + (size_t)row * COUT;
                #pragma unroll
                for (int ni = 0; ni < 8; ni++) {
                    int col = warp_n * 64 + ni * 8 + (lane & 3) * 2;
                    float2 v;
                    v.x = fmaxf(fmaf(acc[mi][ni][h*2+0], s_sc[col],   s_bi[col]),   0.0f);
                    v.y = fmaxf(fmaf(acc[mi][ni][h*2+1], s_sc[col+1], s_bi[col+1]), 0.0f);
                    *(float2*)(op + col) = v;
                }
            }
        }
    }
}

// ---------------------------------------------------------------------------
extern "C" void kernel_launch(void* const* d_in, const int* in_sizes, int n_in,
                              void* d_out, int out_size) {
    const float* p     = (const float*)d_in[0];
    const float* x     = (const float*)d_in[1];
    const float* kp    = (const float*)d_in[2];
    const float* w     = (const float*)d_in[3];
    const float* b     = (const float*)d_in[4];
    const float* gamma = (const float*)d_in[5];
    const float* beta  = (const float*)d_in[6];
    const float* mean  = (const float*)d_in[7];
    const float* var   = (const float*)d_in[8];
    const int*   idx   = (const int*)d_in[9];
    float* out = (float*)d_out;

    cudaFuncSetAttribute(gemm_mma_kernel,
                         cudaFuncAttributeMaxDynamicSharedMemorySize, SMEM_DYN);

    wt_split_kernel<<<(KP2 * COUT + 255) / 256, 256>>>(w);
    preprocess_kernel<<<N_PTS / PPB, 256>>>(p, x, kp, idx);
    gemm_mma_kernel<<<(N_PTS + 127) / 128, 256, SMEM_DYN>>>(
        b, gamma, beta, mean, var, out);
}

// round 9
// speedup vs baseline: 7.0399x; 1.1258x over previous
#include <cuda_runtime.h>
#include <cuda_fp16.h>
#include <cstdint>
#include <math.h>

#define N_PTS 100000
#define KNB   16
#define CIN   128
#define COUT  256
#define NKP   15
#define CXJ   131            // CIN + 3
#define MROW  132            // per-m row: x 0..127, pj 128..130, pad 131
#define KP2   1984           // 15*132 = 1980, padded to 31*64
#define NCHUNK 31
#define PPB   8              // points per block; 100000 = 8*12500

#define XJ_STRIDE 136        // halves per xj row (17 n8-tiles)
#define XJ_ROWB   272        // bytes per row
#define WARP_XJ   (16 * XJ_STRIDE)   // 2176 halves = 4352 B per warp

// ---------------- scratch ----------------------------------------------------
__device__ __align__(128) __half g_agg[(size_t)N_PTS * KP2];
__device__ __align__(128) __half g_wbt[(size_t)KP2 * COUT];

// ---------------- PTX helpers (sm_103 base target only) ---------------------
__device__ __forceinline__ uint32_t smem_u32(const void* p) {
    uint32_t a;
    asm("{ .reg .u64 t; cvta.to.shared.u64 t, %1; cvt.u32.u64 %0, t; }"
        : "=r"(a) : "l"(p));
    return a;
}

__device__ __forceinline__ void cp_async16(uint32_t dst, const void* src,
                                           uint32_t srcsize) {
    asm volatile("cp.async.cg.shared.global [%0], [%1], 16, %2;"
                 :: "r"(dst), "l"(src), "r"(srcsize) : "memory");
}

__device__ __forceinline__ void cp_commit() {
    asm volatile("cp.async.commit_group;" ::: "memory");
}

template <int N>
__device__ __forceinline__ void cp_wait() {
    asm volatile("cp.async.wait_group %0;" :: "n"(N) : "memory");
}

__device__ __forceinline__ void ldsm_x4(uint32_t* r, uint32_t addr) {
    asm volatile("ldmatrix.sync.aligned.m8n8.x4.shared.b16 {%0,%1,%2,%3}, [%4];"
                 : "=r"(r[0]), "=r"(r[1]), "=r"(r[2]), "=r"(r[3]) : "r"(addr));
}

__device__ __forceinline__ void ldsm_x4_t(uint32_t* r, uint32_t addr) {
    asm volatile("ldmatrix.sync.aligned.m8n8.x4.trans.shared.b16 {%0,%1,%2,%3}, [%4];"
                 : "=r"(r[0]), "=r"(r[1]), "=r"(r[2]), "=r"(r[3]) : "r"(addr));
}

__device__ __forceinline__ void ldsm_x2_t(uint32_t* r, uint32_t addr) {
    asm volatile("ldmatrix.sync.aligned.m8n8.x2.trans.shared.b16 {%0,%1}, [%2];"
                 : "=r"(r[0]), "=r"(r[1]) : "r"(addr));
}

__device__ __forceinline__ void mma_fp16(float* c, const uint32_t* a,
                                         const uint32_t* b) {
    asm volatile(
        "mma.sync.aligned.m16n8k16.row.col.f32.f16.f16.f32 "
        "{%0,%1,%2,%3}, {%4,%5,%6,%7}, {%8,%9}, {%0,%1,%2,%3};"
        : "+f"(c[0]), "+f"(c[1]), "+f"(c[2]), "+f"(c[3])
        : "r"(a[0]), "r"(a[1]), "r"(a[2]), "r"(a[3]), "r"(b[0]), "r"(b[1]));
}

// ---------------------------------------------------------------------------
// Weight prep (MROW layout, unchanged from R8)
// ---------------------------------------------------------------------------
__global__ void wt_split_kernel(const float* __restrict__ conv_w) {
    int e = blockIdx.x * blockDim.x + threadIdx.x;
    if (e >= KP2 * COUT) return;
    int col = e / COUT;
    int n   = e - col * COUT;
    float v = 0.0f;
    if (col < NKP * MROW) {
        int m  = col / MROW;
        int nc = col - m * MROW;
        if (nc != 131) {
            int c = (nc < 128) ? (nc + 3) : (nc - 128);
            v = conv_w[((size_t)n * CXJ + c) * NKP + m];
        }
    }
    g_wbt[e] = __float2half_rn(v);
}

// ---------------------------------------------------------------------------
// Preprocess v4: warp-per-point, the 15x136x16 contraction done on tensor cores.
// A-fragment (corr) built directly in registers; xj staged in smem fp16.
// ---------------------------------------------------------------------------
__global__ __launch_bounds__(256) void preprocess_kernel(
    const float* __restrict__ p,
    const float* __restrict__ x,
    const float* __restrict__ kp,
    const int*   __restrict__ idx)
{
    __shared__ __align__(16) __half s_xj[PPB][WARP_XJ];   // 34816 B

    const int wid  = threadIdx.x >> 5;
    const int lane = threadIdx.x & 31;
    const int n    = blockIdx.x * PPB + wid;   // exact: 12500*8

    __half* xj = &s_xj[wid][0];
    const uint32_t xj_b = smem_u32(xj);

    // ---- neighbor indices (lanes 0..15) + relative coords ----
    int idxv = 0;
    if (lane < KNB) idxv = idx[(size_t)n * KNB + lane];

    const float px = p[3 * n + 0];
    const float py = p[3 * n + 1];
    const float pz = p[3 * n + 2];

    float dx = 0.f, dy = 0.f, dz = 0.f, l2 = 0.f;
    if (lane < KNB) {
        dx = p[3 * idxv + 0] - px;
        dy = p[3 * idxv + 1] - py;
        dz = p[3 * idxv + 2] - pz;
        l2 = sqrtf(dx * dx + dy * dy + dz * dz);
    }
    float mx = l2;
    #pragma unroll
    for (int o = 8; o >= 1; o >>= 1)
        mx = fmaxf(mx, __shfl_xor_sync(0xFFFFFFFFu, mx, o));
    const float inv = 1.0f / (mx + 1e-10f);
    const float pjx = dx * inv, pjy = dy * inv, pjz = dz * inv;

    // ---- stage xj rows: x channels (fp16) at cols 0..127 ----
    #pragma unroll
    for (int k = 0; k < KNB; k++) {
        int j = __shfl_sync(0xFFFFFFFFu, idxv, k);
        float4 v = *(const float4*)(x + (size_t)j * CIN + 4 * lane);
        union { uint2 u; __half2 h[2]; } pk;
        pk.h[0] = __floats2half2_rn(v.x, v.y);
        pk.h[1] = __floats2half2_rn(v.z, v.w);
        *(uint2*)(xj + k * XJ_STRIDE + 4 * lane) = pk.u;
    }
    // cols 128..135: pj (3) + zeros (5), one 16B store per row
    if (lane < KNB) {
        union { uint4 u; __half h[8]; } pk;
        pk.u = make_uint4(0u, 0u, 0u, 0u);
        pk.h[0] = __float2half_rn(pjx);
        pk.h[1] = __float2half_rn(pjy);
        pk.h[2] = __float2half_rn(pjz);
        *(uint4*)(xj + lane * XJ_STRIDE + 128) = pk.u;
    }
    __syncwarp();

    // ---- A-fragment (corr) directly in registers ----
    // m16n8k16 A layout: lane l -> rows r=l/4 and r+8; cols k0=2(l%4)+{0,1}, +8
    const int q  = lane & 3;
    const int r  = lane >> 2;
    const int k0 = 2 * q;
    const int kl[4] = { k0, k0 + 1, k0 + 8, k0 + 9 };
    float pax[4], pay[4], paz[4];
    #pragma unroll
    for (int i = 0; i < 4; i++) {
        pax[i] = __shfl_sync(0xFFFFFFFFu, pjx, kl[i]);
        pay[i] = __shfl_sync(0xFFFFFFFFu, pjy, kl[i]);
        paz[i] = __shfl_sync(0xFFFFFFFFu, pjz, kl[i]);
    }
    const float INV_SCALE = (float)(1.0 / (0.3 * 0.3 * 2.0 + 1e-10));
    const bool  mhi_ok = (r + 8) < NKP;          // row 15 is zero padding
    const int   mh = mhi_ok ? (r + 8) : 0;
    const float klx = kp[3 * r + 0], kly = kp[3 * r + 1], klz = kp[3 * r + 2];
    const float khx = kp[3 * mh + 0], khy = kp[3 * mh + 1], khz = kp[3 * mh + 2];

    float clo[4], chi[4];
    #pragma unroll
    for (int i = 0; i < 4; i++) {
        float ax = klx - pax[i], ay = kly - pay[i], az = klz - paz[i];
        clo[i] = __expf(-(ax * ax + ay * ay + az * az) * INV_SCALE);
        float bx = khx - pax[i], by = khy - pay[i], bz = khz - paz[i];
        chi[i] = mhi_ok ? __expf(-(bx * bx + by * by + bz * bz) * INV_SCALE) : 0.f;
    }
    uint32_t afr[4];
    { union { uint32_t u; __half2 h; } t;
      t.h = __floats2half2_rn(clo[0], clo[1]); afr[0] = t.u;
      t.h = __floats2half2_rn(chi[0], chi[1]); afr[1] = t.u;
      t.h = __floats2half2_rn(clo[2], clo[3]); afr[2] = t.u;
      t.h = __floats2half2_rn(chi[2], chi[3]); afr[3] = t.u; }

    // ---- 17 MMAs: agg[16m x 136c] = corr @ xj ----
    float acc[17][4];
    #pragma unroll
    for (int t = 0; t < 17; t++)
        #pragma unroll
        for (int i = 0; i < 4; i++) acc[t][i] = 0.f;

    const uint32_t b_row = xj_b + (uint32_t)(lane & 15) * XJ_ROWB +
                           (uint32_t)(lane >> 4) * 16u;
    #pragma unroll
    for (int nb = 0; nb < 8; nb++) {
        uint32_t t4[4];
        ldsm_x4_t(t4, b_row + (uint32_t)nb * 32u);
        mma_fp16(acc[2 * nb + 0], afr, &t4[0]);
        mma_fp16(acc[2 * nb + 1], afr, &t4[2]);
    }
    {   // last n8 tile: cols 128..135 (16 addresses, lanes 0..15)
        uint32_t t2[2];
        ldsm_x2_t(t2, xj_b + (uint32_t)(lane & 15) * XJ_ROWB + 256u);
        mma_fp16(acc[16], afr, t2);
    }
    __syncwarp();

    // ---- epilogue: C frags -> staging (reuse xj smem), MROW layout ----
    // C layout: lane l -> rows r, r+8; cols 8t + 2q + {0,1}
    __half* stg = xj;
    #pragma unroll
    for (int t = 0; t < 17; t++) {
        int c = 8 * t + 2 * q;
        if (t < 16 || q < 2) {          // skip cols >= 132
            union { uint32_t u; __half2 h; } v;
            v.h = __floats2half2_rn(acc[t][0], acc[t][1]);
            *(uint32_t*)(stg + r * MROW + c) = v.u;
            if (mhi_ok) {
                v.h = __floats2half2_rn(acc[t][2], acc[t][3]);
                *(uint32_t*)(stg + (r + 8) * MROW + c) = v.u;
            }
        }
    }
    if (lane == 0) *(uint2*)(stg + 1980) = make_uint2(0u, 0u);  // tail pad
    __syncwarp();

    // ---- coalesced write-out: 1984 halves = 248 uint4 ----
    __half* dst = g_agg + (size_t)n * KP2;
    #pragma unroll
    for (int i = lane; i < KP2 / 8; i += 32)
        *(uint4*)(dst + 8 * i) = *(const uint4*)(stg + 8 * i);
}

// ---------------------------------------------------------------------------
// GEMM via mma.sync fp16 single-term + cp.async 3-stage pipeline (R8 verbatim)
// ---------------------------------------------------------------------------
#define A_STRIDE 144u
#define B_STRIDE 528u
#define BOFF     18432u
#define STG      52224u
#define NSTAGE   3
#define SMEM_DYN (3u * STG)

__global__ __launch_bounds__(256, 1) void gemm_mma_kernel(
    const float* __restrict__ conv_b,
    const float* __restrict__ bn_gamma,
    const float* __restrict__ bn_beta,
    const float* __restrict__ bn_mean,
    const float* __restrict__ bn_var,
    float* __restrict__ out)
{
    extern __shared__ __align__(1024) char smem[];
    __shared__ __align__(16) float s_sc[COUT];
    __shared__ __align__(16) float s_bi[COUT];

    const uint32_t sb   = smem_u32(smem);
    const int tid    = threadIdx.x;
    const int wid    = tid >> 5;
    const int lane   = tid & 31;
    const int warp_m = wid >> 2;
    const int warp_n = wid & 3;
    const int m0     = blockIdx.x * 128;

    {
        int col = tid;
        float s = bn_gamma[col] * rsqrtf(bn_var[col] + 1e-5f);
        s_sc[col] = s;
        s_bi[col] = (conv_b[col] - bn_mean[col]) * s + bn_beta[col];
    }

    float acc[4][8][4];
    #pragma unroll
    for (int i = 0; i < 4; i++)
        #pragma unroll
        for (int j = 0; j < 8; j++)
            #pragma unroll
            for (int qq = 0; qq < 4; qq++) acc[i][j][qq] = 0.0f;

    auto load_chunk = [&](int c, int stage) {
        const uint32_t base = sb + (uint32_t)stage * STG;
        #pragma unroll
        for (int L = 0; L < 4; L++) {
            int v   = tid + L * 256;
            int row = v >> 3;
            int seg = v & 7;
            int gr  = m0 + row;
            uint32_t ok = (gr < N_PTS) ? 16u : 0u;
            int grc = (gr < N_PTS) ? gr : 0;
            const __half* src = g_agg + (size_t)grc * KP2 + (size_t)c * 64 + seg * 8;
            uint32_t dst = base + (uint32_t)row * A_STRIDE + (uint32_t)seg * 16u;
            cp_async16(dst, src, ok);
        }
        #pragma unroll
        for (int L = 0; L < 8; L++) {
            int v    = tid + L * 256;
            int krow = v >> 5;
            int seg  = v & 31;
            const __half* src = g_wbt + (size_t)(c * 64 + krow) * COUT + seg * 8;
            uint32_t dst = base + BOFF +
                           (uint32_t)krow * B_STRIDE + (uint32_t)seg * 16u;
            cp_async16(dst, src, 16u);
        }
        cp_commit();
    };

    const uint32_t a_base = (uint32_t)(warp_m * 64 + (lane & 15)) * A_STRIDE +
                            (uint32_t)(lane >> 4) * 16u;
    const uint32_t b_base = (uint32_t)(lane & 15) * B_STRIDE + BOFF +
                            (uint32_t)(warp_n * 64 + (lane >> 4) * 8) * 2u;

    load_chunk(0, 0);
    load_chunk(1, 1);

    for (int c = 0; c < NCHUNK; c++) {
        if (c + 2 < NCHUNK) load_chunk(c + 2, (c + 2) % NSTAGE);
        else                cp_commit();
        cp_wait<2>();
        __syncthreads();

        const uint32_t stg = sb + (uint32_t)(c % NSTAGE) * STG;

        #pragma unroll
        for (int ks = 0; ks < 4; ks++) {
            uint32_t ah[4][4];
            #pragma unroll
            for (int mi = 0; mi < 4; mi++) {
                uint32_t aa = stg + a_base + (uint32_t)(mi * 16) * A_STRIDE +
                              (uint32_t)ks * 32u;
                ldsm_x4(ah[mi], aa);
            }
            uint32_t bh[8][2];
            #pragma unroll
            for (int nb = 0; nb < 4; nb++) {
                uint32_t ba = stg + b_base + (uint32_t)(ks * 16) * B_STRIDE +
                              (uint32_t)nb * 32u;
                uint32_t t[4];
                ldsm_x4_t(t, ba);
                bh[2*nb][0] = t[0]; bh[2*nb][1] = t[1];
                bh[2*nb+1][0] = t[2]; bh[2*nb+1][1] = t[3];
            }
            #pragma unroll
            for (int mi = 0; mi < 4; mi++)
                #pragma unroll
                for (int ni = 0; ni < 8; ni++)
                    mma_fp16(acc[mi][ni], ah[mi], bh[ni]);
        }
        __syncthreads();
    }

    const int r_base = m0 + warp_m * 64;
    #pragma unroll
    for (int mi = 0; mi < 4; mi++) {
        #pragma unroll
        for (int h = 0; h < 2; h++) {
            int row = r_base + mi * 16 + (lane >> 2) + h * 8;
            if (row < N_PTS) {
                float* op = out + (size_t)row * COUT;
                #pragma unroll
                for (int ni = 0; ni < 8; ni++) {
                    int col = warp_n * 64 + ni * 8 + (lane & 3) * 2;
                    float2 v;
                    v.x = fmaxf(fmaf(acc[mi][ni][h*2+0], s_sc[col],   s_bi[col]),   0.0f);
                    v.y = fmaxf(fmaf(acc[mi][ni][h*2+1], s_sc[col+1], s_bi[col+1]), 0.0f);
                    *(float2*)(op + col) = v;
                }
            }
        }
    }
}

// ---------------------------------------------------------------------------
extern "C" void kernel_launch(void* const* d_in, const int* in_sizes, int n_in,
                              void* d_out, int out_size) {
    const float* p     = (const float*)d_in[0];
    const float* x     = (const float*)d_in[1];
    const float* kp    = (const float*)d_in[2];
    const float* w     = (const float*)d_in[3];
    const float* b     = (const float*)d_in[4];
    const float* gamma = (const float*)d_in[5];
    const float* beta  = (const float*)d_in[6];
    const float* mean  = (const float*)d_in[7];
    const float* var   = (const float*)d_in[8];
    const int*   idx   = (const int*)d_in[9];
    float* out = (float*)d_out;

    cudaFuncSetAttribute(gemm_mma_kernel,
                         cudaFuncAttributeMaxDynamicSharedMemorySize, SMEM_DYN);

    wt_split_kernel<<<(KP2 * COUT + 255) / 256, 256>>>(w);
    preprocess_kernel<<<N_PTS / PPB, 256>>>(p, x, kp, idx);
    gemm_mma_kernel<<<(N_PTS + 127) / 128, 256, SMEM_DYN>>>(
        b, gamma, beta, mean, var, out);
}

// round 10
// speedup vs baseline: 8.0148x; 1.1385x over previous
#include <cuda_runtime.h>
#include <cuda_fp16.h>
#include <cstdint>
#include <math.h>

#define N_PTS 100000
#define KNB   16
#define CIN   128
#define COUT  256
#define NKP   15
#define CXJ   131            // CIN + 3
#define MROW  132            // per-m row: x 0..127, pj 128..130, pad 131
#define KP2   1984           // 15*132 = 1980, padded to 31*64
#define NCHUNK 31
#define PPB   8              // points per block; 100000 = 8*12500

#define XJ_STRIDE 136        // halves per xj row (17 n8-tiles)
#define XJ_ROWB   272        // bytes per row
#define WARP_XJ   (16 * XJ_STRIDE)   // 2176 halves per warp

// ---------------- scratch ----------------------------------------------------
__device__ __align__(128) __half g_agg[(size_t)N_PTS * KP2];
__device__ __align__(128) __half g_wbt[(size_t)KP2 * COUT];

// ---------------- PTX helpers (sm_103 base target only) ---------------------
__device__ __forceinline__ uint32_t smem_u32(const void* p) {
    uint32_t a;
    asm("{ .reg .u64 t; cvta.to.shared.u64 t, %1; cvt.u32.u64 %0, t; }"
        : "=r"(a) : "l"(p));
    return a;
}

__device__ __forceinline__ void cp_async16(uint32_t dst, const void* src,
                                           uint32_t srcsize) {
    asm volatile("cp.async.cg.shared.global [%0], [%1], 16, %2;"
                 :: "r"(dst), "l"(src), "r"(srcsize) : "memory");
}

__device__ __forceinline__ void cp_commit() {
    asm volatile("cp.async.commit_group;" ::: "memory");
}

template <int N>
__device__ __forceinline__ void cp_wait() {
    asm volatile("cp.async.wait_group %0;" :: "n"(N) : "memory");
}

__device__ __forceinline__ void ldsm_x4(uint32_t* r, uint32_t addr) {
    asm volatile("ldmatrix.sync.aligned.m8n8.x4.shared.b16 {%0,%1,%2,%3}, [%4];"
                 : "=r"(r[0]), "=r"(r[1]), "=r"(r[2]), "=r"(r[3]) : "r"(addr));
}

__device__ __forceinline__ void ldsm_x4_t(uint32_t* r, uint32_t addr) {
    asm volatile("ldmatrix.sync.aligned.m8n8.x4.trans.shared.b16 {%0,%1,%2,%3}, [%4];"
                 : "=r"(r[0]), "=r"(r[1]), "=r"(r[2]), "=r"(r[3]) : "r"(addr));
}

__device__ __forceinline__ void ldsm_x2_t(uint32_t* r, uint32_t addr) {
    asm volatile("ldmatrix.sync.aligned.m8n8.x2.trans.shared.b16 {%0,%1}, [%2];"
                 : "=r"(r[0]), "=r"(r[1]) : "r"(addr));
}

__device__ __forceinline__ void mma_fp16(float* c, const uint32_t* a,
                                         const uint32_t* b) {
    asm volatile(
        "mma.sync.aligned.m16n8k16.row.col.f32.f16.f16.f32 "
        "{%0,%1,%2,%3}, {%4,%5,%6,%7}, {%8,%9}, {%0,%1,%2,%3};"
        : "+f"(c[0]), "+f"(c[1]), "+f"(c[2]), "+f"(c[3])
        : "r"(a[0]), "r"(a[1]), "r"(a[2]), "r"(a[3]), "r"(b[0]), "r"(b[1]));
}

// ---------------------------------------------------------------------------
// Weight prep (MROW layout)
// ---------------------------------------------------------------------------
__global__ void wt_split_kernel(const float* __restrict__ conv_w) {
    int e = blockIdx.x * blockDim.x + threadIdx.x;
    if (e >= KP2 * COUT) return;
    int col = e / COUT;
    int n   = e - col * COUT;
    float v = 0.0f;
    if (col < NKP * MROW) {
        int m  = col / MROW;
        int nc = col - m * MROW;
        if (nc != 131) {
            int c = (nc < 128) ? (nc + 3) : (nc - 128);
            v = conv_w[((size_t)n * CXJ + c) * NKP + m];
        }
    }
    g_wbt[e] = __float2half_rn(v);
}

// ---------------------------------------------------------------------------
// Preprocess v4 (R9 verbatim): warp-per-point tensor-core mini-GEMM
// ---------------------------------------------------------------------------
__global__ __launch_bounds__(256) void preprocess_kernel(
    const float* __restrict__ p,
    const float* __restrict__ x,
    const float* __restrict__ kp,
    const int*   __restrict__ idx)
{
    __shared__ __align__(16) __half s_xj[PPB][WARP_XJ];

    const int wid  = threadIdx.x >> 5;
    const int lane = threadIdx.x & 31;
    const int n    = blockIdx.x * PPB + wid;

    __half* xj = &s_xj[wid][0];
    const uint32_t xj_b = smem_u32(xj);

    int idxv = 0;
    if (lane < KNB) idxv = idx[(size_t)n * KNB + lane];

    const float px = p[3 * n + 0];
    const float py = p[3 * n + 1];
    const float pz = p[3 * n + 2];

    float dx = 0.f, dy = 0.f, dz = 0.f, l2 = 0.f;
    if (lane < KNB) {
        dx = p[3 * idxv + 0] - px;
        dy = p[3 * idxv + 1] - py;
        dz = p[3 * idxv + 2] - pz;
        l2 = sqrtf(dx * dx + dy * dy + dz * dz);
    }
    float mx = l2;
    #pragma unroll
    for (int o = 8; o >= 1; o >>= 1)
        mx = fmaxf(mx, __shfl_xor_sync(0xFFFFFFFFu, mx, o));
    const float inv = 1.0f / (mx + 1e-10f);
    const float pjx = dx * inv, pjy = dy * inv, pjz = dz * inv;

    #pragma unroll
    for (int k = 0; k < KNB; k++) {
        int j = __shfl_sync(0xFFFFFFFFu, idxv, k);
        float4 v = *(const float4*)(x + (size_t)j * CIN + 4 * lane);
        union { uint2 u; __half2 h[2]; } pk;
        pk.h[0] = __floats2half2_rn(v.x, v.y);
        pk.h[1] = __floats2half2_rn(v.z, v.w);
        *(uint2*)(xj + k * XJ_STRIDE + 4 * lane) = pk.u;
    }
    if (lane < KNB) {
        union { uint4 u; __half h[8]; } pk;
        pk.u = make_uint4(0u, 0u, 0u, 0u);
        pk.h[0] = __float2half_rn(pjx);
        pk.h[1] = __float2half_rn(pjy);
        pk.h[2] = __float2half_rn(pjz);
        *(uint4*)(xj + lane * XJ_STRIDE + 128) = pk.u;
    }
    __syncwarp();

    const int q  = lane & 3;
    const int r  = lane >> 2;
    const int k0 = 2 * q;
    const int kl[4] = { k0, k0 + 1, k0 + 8, k0 + 9 };
    float pax[4], pay[4], paz[4];
    #pragma unroll
    for (int i = 0; i < 4; i++) {
        pax[i] = __shfl_sync(0xFFFFFFFFu, pjx, kl[i]);
        pay[i] = __shfl_sync(0xFFFFFFFFu, pjy, kl[i]);
        paz[i] = __shfl_sync(0xFFFFFFFFu, pjz, kl[i]);
    }
    const float INV_SCALE = (float)(1.0 / (0.3 * 0.3 * 2.0 + 1e-10));
    const bool  mhi_ok = (r + 8) < NKP;
    const int   mh = mhi_ok ? (r + 8) : 0;
    const float klx = kp[3 * r + 0], kly = kp[3 * r + 1], klz = kp[3 * r + 2];
    const float khx = kp[3 * mh + 0], khy = kp[3 * mh + 1], khz = kp[3 * mh + 2];

    float clo[4], chi[4];
    #pragma unroll
    for (int i = 0; i < 4; i++) {
        float ax = klx - pax[i], ay = kly - pay[i], az = klz - paz[i];
        clo[i] = __expf(-(ax * ax + ay * ay + az * az) * INV_SCALE);
        float bx = khx - pax[i], by = khy - pay[i], bz = khz - paz[i];
        chi[i] = mhi_ok ? __expf(-(bx * bx + by * by + bz * bz) * INV_SCALE) : 0.f;
    }
    uint32_t afr[4];
    { union { uint32_t u; __half2 h; } t;
      t.h = __floats2half2_rn(clo[0], clo[1]); afr[0] = t.u;
      t.h = __floats2half2_rn(chi[0], chi[1]); afr[1] = t.u;
      t.h = __floats2half2_rn(clo[2], clo[3]); afr[2] = t.u;
      t.h = __floats2half2_rn(chi[2], chi[3]); afr[3] = t.u; }

    float acc[17][4];
    #pragma unroll
    for (int t = 0; t < 17; t++)
        #pragma unroll
        for (int i = 0; i < 4; i++) acc[t][i] = 0.f;

    const uint32_t b_row = xj_b + (uint32_t)(lane & 15) * XJ_ROWB +
                           (uint32_t)(lane >> 4) * 16u;
    #pragma unroll
    for (int nb = 0; nb < 8; nb++) {
        uint32_t t4[4];
        ldsm_x4_t(t4, b_row + (uint32_t)nb * 32u);
        mma_fp16(acc[2 * nb + 0], afr, &t4[0]);
        mma_fp16(acc[2 * nb + 1], afr, &t4[2]);
    }
    {
        uint32_t t2[2];
        ldsm_x2_t(t2, xj_b + (uint32_t)(lane & 15) * XJ_ROWB + 256u);
        mma_fp16(acc[16], afr, t2);
    }
    __syncwarp();

    __half* stg = xj;
    #pragma unroll
    for (int t = 0; t < 17; t++) {
        int c = 8 * t + 2 * q;
        if (t < 16 || q < 2) {
            union { uint32_t u; __half2 h; } v;
            v.h = __floats2half2_rn(acc[t][0], acc[t][1]);
            *(uint32_t*)(stg + r * MROW + c) = v.u;
            if (mhi_ok) {
                v.h = __floats2half2_rn(acc[t][2], acc[t][3]);
                *(uint32_t*)(stg + (r + 8) * MROW + c) = v.u;
            }
        }
    }
    if (lane == 0) *(uint2*)(stg + 1980) = make_uint2(0u, 0u);
    __syncwarp();

    __half* dst = g_agg + (size_t)n * KP2;
    #pragma unroll
    for (int i = lane; i < KP2 / 8; i += 32)
        *(uint4*)(dst + 8 * i) = *(const uint4*)(stg + 8 * i);
}

// ---------------------------------------------------------------------------
// GEMM v2: CTA tile 128(M) x 128(N), 2 CTAs/SM, 3-stage cp.async pipeline
// 8 warps, warp tile 64x32
// ---------------------------------------------------------------------------
#define N_TILE   128
#define A_STRIDE 144u            // (64+8)*2 bytes
#define B_STRIDE 272u            // (128+8)*2 bytes
#define BOFF     18432u          // B after A (128*144)
#define STG      35840u          // 18432 + 64*272
#define NSTAGE   3
#define SMEM_DYN (3u * STG)      // 107520

__global__ __launch_bounds__(256, 2) void gemm_mma_kernel(
    const float* __restrict__ conv_b,
    const float* __restrict__ bn_gamma,
    const float* __restrict__ bn_beta,
    const float* __restrict__ bn_mean,
    const float* __restrict__ bn_var,
    float* __restrict__ out)
{
    extern __shared__ __align__(1024) char smem[];
    __shared__ __align__(16) float s_sc[N_TILE];
    __shared__ __align__(16) float s_bi[N_TILE];

    const uint32_t sb   = smem_u32(smem);
    const int tid    = threadIdx.x;
    const int wid    = tid >> 5;
    const int lane   = tid & 31;
    const int warp_m = wid >> 2;          // 0..1
    const int warp_n = wid & 3;           // 0..3
    const int m0     = blockIdx.x * 128;
    const int n0     = blockIdx.y * N_TILE;

    if (tid < N_TILE) {
        int col = n0 + tid;
        float s = bn_gamma[col] * rsqrtf(bn_var[col] + 1e-5f);
        s_sc[tid] = s;
        s_bi[tid] = (conv_b[col] - bn_mean[col]) * s + bn_beta[col];
    }

    float acc[4][4][4];
    #pragma unroll
    for (int i = 0; i < 4; i++)
        #pragma unroll
        for (int j = 0; j < 4; j++)
            #pragma unroll
            for (int qq = 0; qq < 4; qq++) acc[i][j][qq] = 0.0f;

    auto load_chunk = [&](int c, int stage) {
        const uint32_t base = sb + (uint32_t)stage * STG;
        // A: 128 rows x 8 segs (16B) = 1024 txns
        #pragma unroll
        for (int L = 0; L < 4; L++) {
            int v   = tid + L * 256;
            int row = v >> 3;
            int seg = v & 7;
            int gr  = m0 + row;
            uint32_t ok = (gr < N_PTS) ? 16u : 0u;
            int grc = (gr < N_PTS) ? gr : 0;
            const __half* src = g_agg + (size_t)grc * KP2 + (size_t)c * 64 + seg * 8;
            uint32_t dst = base + (uint32_t)row * A_STRIDE + (uint32_t)seg * 16u;
            cp_async16(dst, src, ok);
        }
        // B: 64 rows x 16 segs (128 cols) = 1024 txns
        #pragma unroll
        for (int L = 0; L < 4; L++) {
            int v    = tid + L * 256;
            int krow = v >> 4;
            int seg  = v & 15;
            const __half* src = g_wbt + (size_t)(c * 64 + krow) * COUT + n0 + seg * 8;
            uint32_t dst = base + BOFF +
                           (uint32_t)krow * B_STRIDE + (uint32_t)seg * 16u;
            cp_async16(dst, src, 16u);
        }
        cp_commit();
    };

    const uint32_t a_base = (uint32_t)(warp_m * 64 + (lane & 15)) * A_STRIDE +
                            (uint32_t)(lane >> 4) * 16u;
    const uint32_t b_base = (uint32_t)(lane & 15) * B_STRIDE + BOFF +
                            (uint32_t)(warp_n * 32 + (lane >> 4) * 8) * 2u;

    load_chunk(0, 0);
    load_chunk(1, 1);

    for (int c = 0; c < NCHUNK; c++) {
        if (c + 2 < NCHUNK) load_chunk(c + 2, (c + 2) % NSTAGE);
        else                cp_commit();
        cp_wait<2>();
        __syncthreads();

        const uint32_t stg = sb + (uint32_t)(c % NSTAGE) * STG;

        #pragma unroll
        for (int ks = 0; ks < 4; ks++) {
            uint32_t ah[4][4];
            #pragma unroll
            for (int mi = 0; mi < 4; mi++) {
                uint32_t aa = stg + a_base + (uint32_t)(mi * 16) * A_STRIDE +
                              (uint32_t)ks * 32u;
                ldsm_x4(ah[mi], aa);
            }
            uint32_t bh[4][2];
            #pragma unroll
            for (int nb = 0; nb < 2; nb++) {
                uint32_t ba = stg + b_base + (uint32_t)(ks * 16) * B_STRIDE +
                              (uint32_t)nb * 32u;
                uint32_t t[4];
                ldsm_x4_t(t, ba);
                bh[2*nb][0] = t[0]; bh[2*nb][1] = t[1];
                bh[2*nb+1][0] = t[2]; bh[2*nb+1][1] = t[3];
            }
            #pragma unroll
            for (int mi = 0; mi < 4; mi++)
                #pragma unroll
                for (int ni = 0; ni < 4; ni++)
                    mma_fp16(acc[mi][ni], ah[mi], bh[ni]);
        }
        __syncthreads();
    }

    // ---- epilogue: bias + BN + ReLU, float2 stores ----
    const int r_base = m0 + warp_m * 64;
    #pragma unroll
    for (int mi = 0; mi < 4; mi++) {
        #pragma unroll
        for (int h = 0; h < 2; h++) {
            int row = r_base + mi * 16 + (lane >> 2) + h * 8;
            if (row < N_PTS) {
                float* op = out + (size_t)row * COUT + n0;
                #pragma unroll
                for (int ni = 0; ni < 4; ni++) {
                    int lc = warp_n * 32 + ni * 8 + (lane & 3) * 2;
                    float2 v;
                    v.x = fmaxf(fmaf(acc[mi][ni][h*2+0], s_sc[lc],   s_bi[lc]),   0.0f);
                    v.y = fmaxf(fmaf(acc[mi][ni][h*2+1], s_sc[lc+1], s_bi[lc+1]), 0.0f);
                    *(float2*)(op + lc) = v;
                }
            }
        }
    }
}

// ---------------------------------------------------------------------------
extern "C" void kernel_launch(void* const* d_in, const int* in_sizes, int n_in,
                              void* d_out, int out_size) {
    const float* p     = (const float*)d_in[0];
    const float* x     = (const float*)d_in[1];
    const float* kp    = (const float*)d_in[2];
    const float* w     = (const float*)d_in[3];
    const float* b     = (const float*)d_in[4];
    const float* gamma = (const float*)d_in[5];
    const float* beta  = (const float*)d_in[6];
    const float* mean  = (const float*)d_in[7];
    const float* var   = (const float*)d_in[8];
    const int*   idx   = (const int*)d_in[9];
    float* out = (float*)d_out;

    cudaFuncSetAttribute(gemm_mma_kernel,
                         cudaFuncAttributeMaxDynamicSharedMemorySize, SMEM_DYN);

    wt_split_kernel<<<(KP2 * COUT + 255) / 256, 256>>>(w);
    preprocess_kernel<<<N_PTS / PPB, 256>>>(p, x, kp, idx);
    dim3 grid((N_PTS + 127) / 128, COUT / N_TILE);
    gemm_mma_kernel<<<grid, 256, SMEM_DYN>>>(b, gamma, beta, mean, var, out);
}

// round 11
// speedup vs baseline: 8.2114x; 1.0245x over previous
#include <cuda_runtime.h>
#include <cuda_fp16.h>
#include <cstdint>
#include <math.h>

#define N_PTS 100000
#define KNB   16
#define CIN   128
#define COUT  256
#define NKP   15
#define CXJ   131            // CIN + 3
#define MROW  132            // per-m row: x 0..127, pj 128..130, pad 131
#define KP2   1984           // 15*132 = 1980, padded to 31*64
#define NCHUNK 31
#define PPB   8              // points per block; 100000 = 8*12500

#define XJ_STRIDE 136        // halves per xj row (17 n8-tiles)
#define XJ_ROWB   272        // bytes per row
#define WARP_XJ   (16 * XJ_STRIDE)   // 2176 halves per warp

// ---------------- scratch ----------------------------------------------------
__device__ __align__(128) __half g_agg[(size_t)N_PTS * KP2];
__device__ __align__(128) __half g_wbt[(size_t)KP2 * COUT];
__device__ __align__(128) __half g_x16[(size_t)N_PTS * CIN];   // fp16 copy of x

// ---------------- PTX helpers (sm_103 base target only) ---------------------
__device__ __forceinline__ uint32_t smem_u32(const void* p) {
    uint32_t a;
    asm("{ .reg .u64 t; cvta.to.shared.u64 t, %1; cvt.u32.u64 %0, t; }"
        : "=r"(a) : "l"(p));
    return a;
}

__device__ __forceinline__ void cp_async16(uint32_t dst, const void* src,
                                           uint32_t srcsize) {
    asm volatile("cp.async.cg.shared.global [%0], [%1], 16, %2;"
                 :: "r"(dst), "l"(src), "r"(srcsize) : "memory");
}

__device__ __forceinline__ void cp_commit() {
    asm volatile("cp.async.commit_group;" ::: "memory");
}

template <int N>
__device__ __forceinline__ void cp_wait() {
    asm volatile("cp.async.wait_group %0;" :: "n"(N) : "memory");
}

__device__ __forceinline__ void ldsm_x4(uint32_t* r, uint32_t addr) {
    asm volatile("ldmatrix.sync.aligned.m8n8.x4.shared.b16 {%0,%1,%2,%3}, [%4];"
                 : "=r"(r[0]), "=r"(r[1]), "=r"(r[2]), "=r"(r[3]) : "r"(addr));
}

__device__ __forceinline__ void ldsm_x4_t(uint32_t* r, uint32_t addr) {
    asm volatile("ldmatrix.sync.aligned.m8n8.x4.trans.shared.b16 {%0,%1,%2,%3}, [%4];"
                 : "=r"(r[0]), "=r"(r[1]), "=r"(r[2]), "=r"(r[3]) : "r"(addr));
}

__device__ __forceinline__ void ldsm_x2_t(uint32_t* r, uint32_t addr) {
    asm volatile("ldmatrix.sync.aligned.m8n8.x2.trans.shared.b16 {%0,%1}, [%2];"
                 : "=r"(r[0]), "=r"(r[1]) : "r"(addr));
}

__device__ __forceinline__ void mma_fp16(float* c, const uint32_t* a,
                                         const uint32_t* b) {
    asm volatile(
        "mma.sync.aligned.m16n8k16.row.col.f32.f16.f16.f32 "
        "{%0,%1,%2,%3}, {%4,%5,%6,%7}, {%8,%9}, {%0,%1,%2,%3};"
        : "+f"(c[0]), "+f"(c[1]), "+f"(c[2]), "+f"(c[3])
        : "r"(a[0]), "r"(a[1]), "r"(a[2]), "r"(a[3]), "r"(b[0]), "r"(b[1]));
}

// ---------------------------------------------------------------------------
// x -> fp16 conversion (same __float2half_rn as the old in-gather convert,
// so results are bit-identical). Each thread converts 8 elements.
// ---------------------------------------------------------------------------
__global__ void xcvt_kernel(const float* __restrict__ x) {
    size_t t = (size_t)blockIdx.x * blockDim.x + threadIdx.x;
    if (t >= (size_t)N_PTS * CIN / 8) return;
    float4 v0 = ((const float4*)x)[2 * t + 0];
    float4 v1 = ((const float4*)x)[2 * t + 1];
    union { uint4 u; __half2 h[4]; } pk;
    pk.h[0] = __floats2half2_rn(v0.x, v0.y);
    pk.h[1] = __floats2half2_rn(v0.z, v0.w);
    pk.h[2] = __floats2half2_rn(v1.x, v1.y);
    pk.h[3] = __floats2half2_rn(v1.z, v1.w);
    ((uint4*)g_x16)[t] = pk.u;
}

// ---------------------------------------------------------------------------
// Weight prep (MROW layout)
// ---------------------------------------------------------------------------
__global__ void wt_split_kernel(const float* __restrict__ conv_w) {
    int e = blockIdx.x * blockDim.x + threadIdx.x;
    if (e >= KP2 * COUT) return;
    int col = e / COUT;
    int n   = e - col * COUT;
    float v = 0.0f;
    if (col < NKP * MROW) {
        int m  = col / MROW;
        int nc = col - m * MROW;
        if (nc != 131) {
            int c = (nc < 128) ? (nc + 3) : (nc - 128);
            v = conv_w[((size_t)n * CXJ + c) * NKP + m];
        }
    }
    g_wbt[e] = __float2half_rn(v);
}

// ---------------------------------------------------------------------------
// Preprocess v5: warp-per-point tensor-core mini-GEMM; gathers fp16 x rows
// ---------------------------------------------------------------------------
__global__ __launch_bounds__(256) void preprocess_kernel(
    const float* __restrict__ p,
    const float* __restrict__ kp,
    const int*   __restrict__ idx)
{
    __shared__ __align__(16) __half s_xj[PPB][WARP_XJ];

    const int wid  = threadIdx.x >> 5;
    const int lane = threadIdx.x & 31;
    const int n    = blockIdx.x * PPB + wid;

    __half* xj = &s_xj[wid][0];
    const uint32_t xj_b = smem_u32(xj);

    int idxv = 0;
    if (lane < KNB) idxv = idx[(size_t)n * KNB + lane];

    const float px = p[3 * n + 0];
    const float py = p[3 * n + 1];
    const float pz = p[3 * n + 2];

    float dx = 0.f, dy = 0.f, dz = 0.f, l2 = 0.f;
    if (lane < KNB) {
        dx = p[3 * idxv + 0] - px;
        dy = p[3 * idxv + 1] - py;
        dz = p[3 * idxv + 2] - pz;
        l2 = sqrtf(dx * dx + dy * dy + dz * dz);
    }
    float mx = l2;
    #pragma unroll
    for (int o = 8; o >= 1; o >>= 1)
        mx = fmaxf(mx, __shfl_xor_sync(0xFFFFFFFFu, mx, o));
    const float inv = 1.0f / (mx + 1e-10f);
    const float pjx = dx * inv, pjy = dy * inv, pjz = dz * inv;

    // ---- gather fp16 x rows: 16 rows x 16 uint4 segs = 256 units ----
    #pragma unroll
    for (int i = 0; i < 8; i++) {
        int v   = lane + 32 * i;       // 0..255
        int row = v >> 4;
        int seg = v & 15;
        int j = __shfl_sync(0xFFFFFFFFu, idxv, row);
        uint4 d = *(const uint4*)(g_x16 + (size_t)j * CIN + 8 * seg);
        *(uint4*)(xj + row * XJ_STRIDE + 8 * seg) = d;
    }
    // cols 128..135: pj (3) + zeros (5)
    if (lane < KNB) {
        union { uint4 u; __half h[8]; } pk;
        pk.u = make_uint4(0u, 0u, 0u, 0u);
        pk.h[0] = __float2half_rn(pjx);
        pk.h[1] = __float2half_rn(pjy);
        pk.h[2] = __float2half_rn(pjz);
        *(uint4*)(xj + lane * XJ_STRIDE + 128) = pk.u;
    }
    __syncwarp();

    // ---- A-fragment (corr) directly in registers ----
    const int q  = lane & 3;
    const int r  = lane >> 2;
    const int k0 = 2 * q;
    const int kl[4] = { k0, k0 + 1, k0 + 8, k0 + 9 };
    float pax[4], pay[4], paz[4];
    #pragma unroll
    for (int i = 0; i < 4; i++) {
        pax[i] = __shfl_sync(0xFFFFFFFFu, pjx, kl[i]);
        pay[i] = __shfl_sync(0xFFFFFFFFu, pjy, kl[i]);
        paz[i] = __shfl_sync(0xFFFFFFFFu, pjz, kl[i]);
    }
    const float INV_SCALE = (float)(1.0 / (0.3 * 0.3 * 2.0 + 1e-10));
    const bool  mhi_ok = (r + 8) < NKP;
    const int   mh = mhi_ok ? (r + 8) : 0;
    const float klx = kp[3 * r + 0], kly = kp[3 * r + 1], klz = kp[3 * r + 2];
    const float khx = kp[3 * mh + 0], khy = kp[3 * mh + 1], khz = kp[3 * mh + 2];

    float clo[4], chi[4];
    #pragma unroll
    for (int i = 0; i < 4; i++) {
        float ax = klx - pax[i], ay = kly - pay[i], az = klz - paz[i];
        clo[i] = __expf(-(ax * ax + ay * ay + az * az) * INV_SCALE);
        float bx = khx - pax[i], by = khy - pay[i], bz = khz - paz[i];
        chi[i] = mhi_ok ? __expf(-(bx * bx + by * by + bz * bz) * INV_SCALE) : 0.f;
    }
    uint32_t afr[4];
    { union { uint32_t u; __half2 h; } t;
      t.h = __floats2half2_rn(clo[0], clo[1]); afr[0] = t.u;
      t.h = __floats2half2_rn(chi[0], chi[1]); afr[1] = t.u;
      t.h = __floats2half2_rn(clo[2], clo[3]); afr[2] = t.u;
      t.h = __floats2half2_rn(chi[2], chi[3]); afr[3] = t.u; }

    float acc[17][4];
    #pragma unroll
    for (int t = 0; t < 17; t++)
        #pragma unroll
        for (int i = 0; i < 4; i++) acc[t][i] = 0.f;

    const uint32_t b_row = xj_b + (uint32_t)(lane & 15) * XJ_ROWB +
                           (uint32_t)(lane >> 4) * 16u;
    #pragma unroll
    for (int nb = 0; nb < 8; nb++) {
        uint32_t t4[4];
        ldsm_x4_t(t4, b_row + (uint32_t)nb * 32u);
        mma_fp16(acc[2 * nb + 0], afr, &t4[0]);
        mma_fp16(acc[2 * nb + 1], afr, &t4[2]);
    }
    {
        uint32_t t2[2];
        ldsm_x2_t(t2, xj_b + (uint32_t)(lane & 15) * XJ_ROWB + 256u);
        mma_fp16(acc[16], afr, t2);
    }
    __syncwarp();

    __half* stg = xj;
    #pragma unroll
    for (int t = 0; t < 17; t++) {
        int c = 8 * t + 2 * q;
        if (t < 16 || q < 2) {
            union { uint32_t u; __half2 h; } v;
            v.h = __floats2half2_rn(acc[t][0], acc[t][1]);
            *(uint32_t*)(stg + r * MROW + c) = v.u;
            if (mhi_ok) {
                v.h = __floats2half2_rn(acc[t][2], acc[t][3]);
                *(uint32_t*)(stg + (r + 8) * MROW + c) = v.u;
            }
        }
    }
    if (lane == 0) *(uint2*)(stg + 1980) = make_uint2(0u, 0u);
    __syncwarp();

    __half* dst = g_agg + (size_t)n * KP2;
    #pragma unroll
    for (int i = lane; i < KP2 / 8; i += 32)
        *(uint4*)(dst + 8 * i) = *(const uint4*)(stg + 8 * i);
}

// ---------------------------------------------------------------------------
// GEMM (R10 verbatim): 128x128 tile, 2 CTAs/SM, 3-stage cp.async pipeline
// ---------------------------------------------------------------------------
#define N_TILE   128
#define A_STRIDE 144u
#define B_STRIDE 272u
#define BOFF     18432u
#define STG      35840u
#define NSTAGE   3
#define SMEM_DYN (3u * STG)

__global__ __launch_bounds__(256, 2) void gemm_mma_kernel(
    const float* __restrict__ conv_b,
    const float* __restrict__ bn_gamma,
    const float* __restrict__ bn_beta,
    const float* __restrict__ bn_mean,
    const float* __restrict__ bn_var,
    float* __restrict__ out)
{
    extern __shared__ __align__(1024) char smem[];
    __shared__ __align__(16) float s_sc[N_TILE];
    __shared__ __align__(16) float s_bi[N_TILE];

    const uint32_t sb   = smem_u32(smem);
    const int tid    = threadIdx.x;
    const int wid    = tid >> 5;
    const int lane   = tid & 31;
    const int warp_m = wid >> 2;
    const int warp_n = wid & 3;
    const int m0     = blockIdx.x * 128;
    const int n0     = blockIdx.y * N_TILE;

    if (tid < N_TILE) {
        int col = n0 + tid;
        float s = bn_gamma[col] * rsqrtf(bn_var[col] + 1e-5f);
        s_sc[tid] = s;
        s_bi[tid] = (conv_b[col] - bn_mean[col]) * s + bn_beta[col];
    }

    float acc[4][4][4];
    #pragma unroll
    for (int i = 0; i < 4; i++)
        #pragma unroll
        for (int j = 0; j < 4; j++)
            #pragma unroll
            for (int qq = 0; qq < 4; qq++) acc[i][j][qq] = 0.0f;

    auto load_chunk = [&](int c, int stage) {
        const uint32_t base = sb + (uint32_t)stage * STG;
        #pragma unroll
        for (int L = 0; L < 4; L++) {
            int v   = tid + L * 256;
            int row = v >> 3;
            int seg = v & 7;
            int gr  = m0 + row;
            uint32_t ok = (gr < N_PTS) ? 16u : 0u;
            int grc = (gr < N_PTS) ? gr : 0;
            const __half* src = g_agg + (size_t)grc * KP2 + (size_t)c * 64 + seg * 8;
            uint32_t dst = base + (uint32_t)row * A_STRIDE + (uint32_t)seg * 16u;
            cp_async16(dst, src, ok);
        }
        #pragma unroll
        for (int L = 0; L < 4; L++) {
            int v    = tid + L * 256;
            int krow = v >> 4;
            int seg  = v & 15;
            const __half* src = g_wbt + (size_t)(c * 64 + krow) * COUT + n0 + seg * 8;
            uint32_t dst = base + BOFF +
                           (uint32_t)krow * B_STRIDE + (uint32_t)seg * 16u;
            cp_async16(dst, src, 16u);
        }
        cp_commit();
    };

    const uint32_t a_base = (uint32_t)(warp_m * 64 + (lane & 15)) * A_STRIDE +
                            (uint32_t)(lane >> 4) * 16u;
    const uint32_t b_base = (uint32_t)(lane & 15) * B_STRIDE + BOFF +
                            (uint32_t)(warp_n * 32 + (lane >> 4) * 8) * 2u;

    load_chunk(0, 0);
    load_chunk(1, 1);

    for (int c = 0; c < NCHUNK; c++) {
        if (c + 2 < NCHUNK) load_chunk(c + 2, (c + 2) % NSTAGE);
        else                cp_commit();
        cp_wait<2>();
        __syncthreads();

        const uint32_t stg = sb + (uint32_t)(c % NSTAGE) * STG;

        #pragma unroll
        for (int ks = 0; ks < 4; ks++) {
            uint32_t ah[4][4];
            #pragma unroll
            for (int mi = 0; mi < 4; mi++) {
                uint32_t aa = stg + a_base + (uint32_t)(mi * 16) * A_STRIDE +
                              (uint32_t)ks * 32u;
                ldsm_x4(ah[mi], aa);
            }
            uint32_t bh[4][2];
            #pragma unroll
            for (int nb = 0; nb < 2; nb++) {
                uint32_t ba = stg + b_base + (uint32_t)(ks * 16) * B_STRIDE +
                              (uint32_t)nb * 32u;
                uint32_t t[4];
                ldsm_x4_t(t, ba);
                bh[2*nb][0] = t[0]; bh[2*nb][1] = t[1];
                bh[2*nb+1][0] = t[2]; bh[2*nb+1][1] = t[3];
            }
            #pragma unroll
            for (int mi = 0; mi < 4; mi++)
                #pragma unroll
                for (int ni = 0; ni < 4; ni++)
                    mma_fp16(acc[mi][ni], ah[mi], bh[ni]);
        }
        __syncthreads();
    }

    const int r_base = m0 + warp_m * 64;
    #pragma unroll
    for (int mi = 0; mi < 4; mi++) {
        #pragma unroll
        for (int h = 0; h < 2; h++) {
            int row = r_base + mi * 16 + (lane >> 2) + h * 8;
            if (row < N_PTS) {
                float* op = out + (size_t)row * COUT + n0;
                #pragma unroll
                for (int ni = 0; ni < 4; ni++) {
                    int lc = warp_n * 32 + ni * 8 + (lane & 3) * 2;
                    float2 v;
                    v.x = fmaxf(fmaf(acc[mi][ni][h*2+0], s_sc[lc],   s_bi[lc]),   0.0f);
                    v.y = fmaxf(fmaf(acc[mi][ni][h*2+1], s_sc[lc+1], s_bi[lc+1]), 0.0f);
                    *(float2*)(op + lc) = v;
                }
            }
        }
    }
}

// ---------------------------------------------------------------------------
extern "C" void kernel_launch(void* const* d_in, const int* in_sizes, int n_in,
                              void* d_out, int out_size) {
    const float* p     = (const float*)d_in[0];
    const float* x     = (const float*)d_in[1];
    const float* kp    = (const float*)d_in[2];
    const float* w     = (const float*)d_in[3];
    const float* b     = (const float*)d_in[4];
    const float* gamma = (const float*)d_in[5];
    const float* beta  = (const float*)d_in[6];
    const float* mean  = (const float*)d_in[7];
    const float* var   = (const float*)d_in[8];
    const int*   idx   = (const int*)d_in[9];
    float* out = (float*)d_out;

    cudaFuncSetAttribute(gemm_mma_kernel,
                         cudaFuncAttributeMaxDynamicSharedMemorySize, SMEM_DYN);

    xcvt_kernel<<<(N_PTS * CIN / 8 + 255) / 256, 256>>>(x);
    wt_split_kernel<<<(KP2 * COUT + 255) / 256, 256>>>(w);
    preprocess_kernel<<<N_PTS / PPB, 256>>>(p, kp, idx);
    dim3 grid((N_PTS + 127) / 128, COUT / N_TILE);
    gemm_mma_kernel<<<grid, 256, SMEM_DYN>>>(b, gamma, beta, mean, var, out);
}